// round 15
// baseline (speedup 1.0000x reference)
#include <cuda_runtime.h>
#include <cuda_bf16.h>
#include <cuda_fp16.h>
#include <cstddef>
#include <cstdint>

// ---------------------------------------------------------------------------
// GcnNet restructured (round 15):
//   CSR  = counting-sort of adj edges by row (multi-block scan); spmm4 fused
//   h1   = relu(AF @ w1 + b1); h1cat -> d_out; PLUS dense fp16 copy h1h
//   AH1  = csr-spmm(adj, h1h) -> fp16 single
//   FUSED h2+Z kernel:
//     phase1: h2 tile = relu(AH1 @ w2[:128] + AF @ w2[128:] + b2)  -> SMEM
//     phase2: Z tile  = h2 tile @ w3[0:256]                        -> fp16
//     (fp16 mma, B in hi/lo split, 2 MMAs per step)
//   h3[i]= relu(bv[i]*Z[bc[i]] + x3[i] @ w3[256:260] + b3) (warp-per-point
//          unpool, fused h4, streaming stores)
// Output layout (floats): [logits | h1cat | h2_out(=h3) | h3_cat | h4]
// ---------------------------------------------------------------------------

#define N_POOL   100000
#define N_POINTS 400000
#define N_EDGES  3200000
#define M_PAD    100096   // 782 * 128
#define SCAN_B   98       // ceil(100000/1024)

static const size_t OFF_LOGITS = 0;
static const size_t OFF_H1     = (size_t)N_POINTS * 4;
static const size_t OFF_H2OUT  = OFF_H1 + (size_t)N_POOL * 132;
static const size_t OFF_H3CAT  = OFF_H2OUT + (size_t)N_POINTS * 512;
static const size_t OFF_H4     = OFF_H3CAT + (size_t)N_POINTS * 516;

// scratch (no cudaMalloc allowed). __device__ globals are zero-initialized.
__device__ float g_AF[(size_t)N_POOL * 4];
__device__ int   g_cnt[N_POOL];
__device__ int   g_rowptr[N_POOL + 1];
__device__ int   g_fill[N_POOL];
__device__ int   g_bsum[SCAN_B];
__device__ int2  g_edge[N_EDGES];   // (col, val-as-int)
__device__ __half g_h1h[(size_t)N_POOL * 128];   // dense fp16 gather copy
__device__ __half g_AH1h[(size_t)M_PAD * 128];   // fp16 single
__device__ __half g_Wt2hi[(size_t)256 * 128];    // w2[0:128]^T K-contig fp16 hi
__device__ __half g_Wt2lo[(size_t)256 * 128];    // fp16 lo
__device__ __half g_Wthi[(size_t)512 * 256];     // w3[0:256]^T K-contig fp16 hi
__device__ __half g_Wtlo[(size_t)512 * 256];     // fp16 lo
__device__ __half g_Zh[(size_t)N_POOL * 512];    // Z in fp16 (L2-resident)

// ------------------------------ helpers ------------------------------------
__device__ __forceinline__ uint32_t smem_to_u32(const void* p) {
    uint32_t a;
    asm("{ .reg .u64 t; cvta.to.shared.u64 t, %1; cvt.u32.u64 %0, t; }" : "=r"(a) : "l"(p));
    return a;
}
__device__ __forceinline__ void ldsm_x4(uint32_t& r0, uint32_t& r1, uint32_t& r2, uint32_t& r3,
                                        uint32_t addr) {
    asm volatile("ldmatrix.sync.aligned.m8n8.x4.shared.b16 {%0,%1,%2,%3}, [%4];"
                 : "=r"(r0), "=r"(r1), "=r"(r2), "=r"(r3) : "r"(addr));
}
__device__ __forceinline__ void mma_f16(float& c0, float& c1, float& c2, float& c3,
                                        uint32_t a0, uint32_t a1, uint32_t a2, uint32_t a3,
                                        uint32_t b0, uint32_t b1) {
    asm volatile("mma.sync.aligned.m16n8k16.row.col.f32.f16.f16.f32 "
                 "{%0,%1,%2,%3}, {%4,%5,%6,%7}, {%8,%9}, {%0,%1,%2,%3};"
                 : "+f"(c0), "+f"(c1), "+f"(c2), "+f"(c3)
                 : "r"(a0), "r"(a1), "r"(a2), "r"(a3), "r"(b0), "r"(b1));
}
__device__ __forceinline__ void red_add_v4(float* p, float a, float b, float c, float d) {
    asm volatile("red.global.add.v4.f32 [%0], {%1, %2, %3, %4};"
                 :: "l"(p), "f"(a), "f"(b), "f"(c), "f"(d) : "memory");
}
__device__ __forceinline__ void stcs4(float* p, float4 v) {
    asm volatile("st.global.cs.v4.f32 [%0], {%1, %2, %3, %4};"
                 :: "l"(p), "f"(v.x), "f"(v.y), "f"(v.z), "f"(v.w) : "memory");
}

// --------------------------- CSR build -------------------------------------
__global__ void count_kernel(const int* __restrict__ keys, int* __restrict__ cnt, int n) {
    int e = blockIdx.x * blockDim.x + threadIdx.x;
    if (e < n) atomicAdd(cnt + __ldg(keys + e), 1);
}

__global__ void scan_reduce(const int* __restrict__ cnt, int* __restrict__ bsum, int n) {
    __shared__ int s[32];
    int tid = threadIdx.x, lane = tid & 31, wid = tid >> 5;
    int i = blockIdx.x * 1024 + tid;
    int v = (i < n) ? cnt[i] : 0;
#pragma unroll
    for (int off = 16; off > 0; off >>= 1) v += __shfl_down_sync(0xFFFFFFFFu, v, off);
    if (lane == 0) s[wid] = v;
    __syncthreads();
    if (wid == 0) {
        int x = s[lane];
#pragma unroll
        for (int off = 16; off > 0; off >>= 1) x += __shfl_down_sync(0xFFFFFFFFu, x, off);
        if (lane == 0) bsum[blockIdx.x] = x;
    }
}

__global__ void scan_tops(int* __restrict__ bsum, int* __restrict__ rowptr_last, int nb) {
    __shared__ int s[128];
    int t = threadIdx.x;  // 128 threads
    int v = (t < nb) ? bsum[t] : 0;
    s[t] = v;
    __syncthreads();
    for (int off = 1; off < 128; off <<= 1) {
        int x = (t >= off) ? s[t - off] : 0;
        __syncthreads();
        s[t] += x;
        __syncthreads();
    }
    if (t < nb) bsum[t] = s[t] - v;             // exclusive
    if (t == nb - 1) *rowptr_last = s[t];       // total -> rowptr[N_POOL]
}

__global__ void scan_final(const int* __restrict__ cnt, const int* __restrict__ bsum,
                           int* __restrict__ rowptr, int* __restrict__ fill, int n) {
    __shared__ int ws[32];
    int tid = threadIdx.x, lane = tid & 31, wid = tid >> 5;
    int i = blockIdx.x * 1024 + tid;
    int v = (i < n) ? cnt[i] : 0;
    int inc = v;
#pragma unroll
    for (int off = 1; off < 32; off <<= 1) {
        int x = __shfl_up_sync(0xFFFFFFFFu, inc, off);
        if (lane >= off) inc += x;
    }
    if (lane == 31) ws[wid] = inc;
    __syncthreads();
    if (wid == 0) {
        int x = ws[lane];
#pragma unroll
        for (int off = 1; off < 32; off <<= 1) {
            int y = __shfl_up_sync(0xFFFFFFFFu, x, off);
            if (lane >= off) x += y;
        }
        ws[lane] = x;
    }
    __syncthreads();
    int woff = (wid > 0) ? ws[wid - 1] : 0;
    if (i < n) {
        int p = inc - v + woff + __ldg(bsum + blockIdx.x);
        rowptr[i] = p;
        fill[i] = p;
    }
}

// edge scatter (packed int2) fused with spmm4 (AF = A @ feature)
__global__ void build_kernel(const int* __restrict__ rows, const int* __restrict__ cols,
                             const float* __restrict__ vals, int* __restrict__ fill,
                             int2* __restrict__ edge,
                             const float* __restrict__ F, float* __restrict__ AF, int nE) {
    int e = blockIdx.x * blockDim.x + threadIdx.x;
    if (e >= nE) return;
    int r = __ldg(rows + e);
    int c = __ldg(cols + e);
    float v = __ldg(vals + e);
    int pos = atomicAdd(fill + r, 1);
    edge[pos] = make_int2(c, __float_as_int(v));
    float4 f = *(const float4*)(F + (size_t)c * 4);
    red_add_v4(AF + (size_t)r * 4, v * f.x, v * f.y, v * f.z, v * f.w);
}

// ------------- K2: h1 = relu(AF@w1+b1) -> h1cat + dense fp16 copy ----------
__global__ void h1_kernel(const float* __restrict__ AF, const float* __restrict__ F,
                          const float* __restrict__ w1, const float* __restrict__ b1,
                          float* __restrict__ out_h1, __half* __restrict__ h1h) {
    int r = blockIdx.x;
    int j = threadIdx.x;  // 128
    float4 a = *(const float4*)(AF + (size_t)r * 4);
    float s = __ldg(b1 + j)
            + a.x * __ldg(w1 + j)
            + a.y * __ldg(w1 + 128 + j)
            + a.z * __ldg(w1 + 256 + j)
            + a.w * __ldg(w1 + 384 + j);
    s = fmaxf(s, 0.f);
    float* row = out_h1 + (size_t)r * 132;
    row[j] = s;
    h1h[(size_t)r * 128 + j] = __float2half(s);
    if (j < 4) row[128 + j] = F[(size_t)r * 4 + j];
}

// ----------------- K3: AH1 = csr-spmm(adj, h1h) -> fp16 single -------------
__global__ __launch_bounds__(256)
void spmm128_csr(const int* __restrict__ rowptr, const int2* __restrict__ edge,
                 const __half* __restrict__ h1h, __half* __restrict__ AH1h) {
    int r = (blockIdx.x * blockDim.x + threadIdx.x) >> 5;
    if (r >= N_POOL) return;
    int lane = threadIdx.x & 31;
    int start = __ldg(rowptr + r), end = __ldg(rowptr + r + 1);
    float4 acc = make_float4(0.f, 0.f, 0.f, 0.f);
    const int loff = lane * 4;
    for (int base = start; base < end; base += 32) {
        int n = min(32, end - base);
        int2 ev = make_int2(0, 0);
        if (lane < n) ev = __ldg(edge + base + lane);
        int j = 0;
        for (; j + 8 <= n; j += 8) {
            int cc[8]; float vv[8]; uint2 uu[8];
#pragma unroll
            for (int q = 0; q < 8; q++) {
                cc[q] = __shfl_sync(0xFFFFFFFFu, ev.x, j + q);
                vv[q] = __int_as_float(__shfl_sync(0xFFFFFFFFu, ev.y, j + q));
            }
#pragma unroll
            for (int q = 0; q < 8; q++)
                uu[q] = *(const uint2*)(h1h + (size_t)cc[q] * 128 + loff);
#pragma unroll
            for (int q = 0; q < 8; q++) {
                float2 f01 = __half22float2(*reinterpret_cast<__half2*>(&uu[q].x));
                float2 f23 = __half22float2(*reinterpret_cast<__half2*>(&uu[q].y));
                acc.x += vv[q] * f01.x;
                acc.y += vv[q] * f01.y;
                acc.z += vv[q] * f23.x;
                acc.w += vv[q] * f23.y;
            }
        }
        for (; j < n; j++) {
            int cj = __shfl_sync(0xFFFFFFFFu, ev.x, j);
            float vj = __int_as_float(__shfl_sync(0xFFFFFFFFu, ev.y, j));
            uint2 u = *(const uint2*)(h1h + (size_t)cj * 128 + loff);
            float2 f01 = __half22float2(*reinterpret_cast<__half2*>(&u.x));
            float2 f23 = __half22float2(*reinterpret_cast<__half2*>(&u.y));
            acc.x += vj * f01.x; acc.y += vj * f01.y;
            acc.z += vj * f23.x; acc.w += vj * f23.y;
        }
    }
    union { __half2 h2[2]; uint2 u; } p;
    p.h2[0] = __floats2half2_rn(acc.x, acc.y);
    p.h2[1] = __floats2half2_rn(acc.z, acc.w);
    *(uint2*)(AH1h + (size_t)r * 128 + loff) = p.u;
}

// ---------------- converts: weights^T to fp16 hi/lo ------------------------
__global__ void convert_w3_kernel(const float* __restrict__ w3,
                                  __half* __restrict__ hi, __half* __restrict__ lo) {
    int t = blockIdx.x * blockDim.x + threadIdx.x;
    if (t >= 512 * 256) return;
    int n = t >> 8, k = t & 255;
    float v = __ldg(w3 + (size_t)k * 512 + n);
    __half h = __float2half_rn(v);
    hi[t] = h;
    lo[t] = __float2half_rn(v - __half2float(h));
}
__global__ void convert_w2_kernel(const float* __restrict__ w2,
                                  __half* __restrict__ hi, __half* __restrict__ lo) {
    int t = blockIdx.x * blockDim.x + threadIdx.x;
    if (t >= 256 * 128) return;
    int n = t >> 7, k = t & 127;
    float v = __ldg(w2 + (size_t)k * 256 + n);
    __half h = __float2half_rn(v);
    hi[t] = h;
    lo[t] = __float2half_rn(v - __half2float(h));
}

// ===========================================================================
// FUSED K4+K5: per 128-row M tile:
//   phase1: H2 tile (128x256 fp16) = relu(AH1@w2a + AF@w2b + b2)  -> SMEM
//   phase2: Z tile (128x512 fp16)  = H2 tile @ w3a                -> global
// 8 warps (2x4), warp 64x32, BK=32, fp16 mma, B hi/lo (2 MMAs).
// ===========================================================================
#define ZS_STRIDE 40
#define ZS_TBYTES (128 * ZS_STRIDE * 2)   // 10240
#define ZS_STAGE  (3 * ZS_TBYTES)         // A,Bhi,Blo
#define ZS_TOTAL  (2 * ZS_STAGE)          // 61440
#define H2S_STRIDE 264                    // halves; pad 8
#define H2S_BYTES (128 * H2S_STRIDE * 2)  // 67584
#define FUSED_SMEM (ZS_TOTAL + H2S_BYTES) // 129024

__global__ __launch_bounds__(256)
void gemm25_mma(const __half* __restrict__ A, const __half* __restrict__ B2hi,
                const __half* __restrict__ B2lo,
                const __half* __restrict__ B3hi, const __half* __restrict__ B3lo,
                const float* __restrict__ AF, const float* __restrict__ w2,
                const float* __restrict__ b2, __half* __restrict__ Zh, int M) {
    extern __shared__ char sm[];
    __half* smH2 = (__half*)(sm + ZS_TOTAL);
    const int tid = threadIdx.x;
    const int lane = tid & 31, wid = tid >> 5;
    const int warp_m = (wid & 1) * 64;
    const int warp_n = (wid >> 1) * 32;
    const int row0 = blockIdx.x * 128;
    const uint32_t sb = smem_to_u32(sm);
    const uint32_t sbH2 = sb + ZS_TOTAL;

    const int st_row = tid >> 2;
    const int st_c8  = (tid & 3) << 3;

    const int a_row_l = (lane & 7) + ((lane >> 3) & 1) * 8;
    const int a_col_l = (lane >> 4) * 8;
    const int b_row_l = lane & 7;
    const int b_n_l   = (lane >> 4) * 8;
    const int b_k_l   = ((lane >> 3) & 1) * 8;
    const int er = lane >> 2, ec = (lane & 3) * 2;

    // AF rows for the epilogue tail (same for both phase-1 passes)
    float4 af[4][2];
#pragma unroll
    for (int mf = 0; mf < 4; mf++) {
        int r0g = row0 + warp_m + mf * 16 + er;
        af[mf][0] = (r0g < M)     ? *(const float4*)(AF + (size_t)r0g * 4)       : make_float4(0, 0, 0, 0);
        af[mf][1] = (r0g + 8 < M) ? *(const float4*)(AF + (size_t)(r0g + 8) * 4) : make_float4(0, 0, 0, 0);
    }

    float acc[4][4][4];

    // ======================= phase 1: H2 tile ============================
    for (int np = 0; np < 2; np++) {
        const int colg = np * 128;  // H2 column base (w2 N range)
#pragma unroll
        for (int i = 0; i < 4; i++)
#pragma unroll
            for (int j = 0; j < 4; j++)
#pragma unroll
                for (int q = 0; q < 4; q++) acc[i][j][q] = 0.f;

        auto stage1 = [&](int kt, int buf) {
            const int k0 = kt * 32;
            char* base = sm + buf * ZS_STAGE;
#pragma unroll
            for (int it = 0; it < 2; it++) {
                int row = st_row + it * 64;
                size_t ga = (size_t)(row0 + row) * 128 + k0 + st_c8;
                size_t gb = (size_t)(colg + row) * 128 + k0 + st_c8;
                uint32_t so = (uint32_t)(row * ZS_STRIDE + st_c8) * 2;
                *(uint4*)(base + 0 * ZS_TBYTES + so) = *(const uint4*)(A + ga);
                *(uint4*)(base + 1 * ZS_TBYTES + so) = *(const uint4*)(B2hi + gb);
                *(uint4*)(base + 2 * ZS_TBYTES + so) = *(const uint4*)(B2lo + gb);
            }
        };

        stage1(0, 0);
        __syncthreads();
        for (int kt = 0; kt < 4; kt++) {
            if (kt < 3) stage1(kt + 1, (kt + 1) & 1);
            const uint32_t abase = sb + (kt & 1) * ZS_STAGE;
            const uint32_t bbase = abase + 1 * ZS_TBYTES;
#pragma unroll
            for (int ks = 0; ks < 2; ks++) {
                const int kl = ks * 16;
                uint32_t av[4][4];
#pragma unroll
                for (int mf = 0; mf < 4; mf++) {
                    uint32_t ao = abase +
                        (uint32_t)((warp_m + mf * 16 + a_row_l) * ZS_STRIDE + kl + a_col_l) * 2;
                    ldsm_x4(av[mf][0], av[mf][1], av[mf][2], av[mf][3], ao);
                }
                uint32_t bh[2][4], bl[2][4];
#pragma unroll
                for (int ng = 0; ng < 2; ng++) {
                    uint32_t bo = bbase +
                        (uint32_t)((warp_n + ng * 16 + b_n_l + b_row_l) * ZS_STRIDE + kl + b_k_l) * 2;
                    ldsm_x4(bh[ng][0], bh[ng][1], bh[ng][2], bh[ng][3], bo);
                    ldsm_x4(bl[ng][0], bl[ng][1], bl[ng][2], bl[ng][3], bo + ZS_TBYTES);
                }
#pragma unroll
                for (int mf = 0; mf < 4; mf++) {
#pragma unroll
                    for (int n = 0; n < 4; n++) {
                        const int ng = n >> 1, hf = (n & 1) * 2;
                        float* c = acc[mf][n];
                        mma_f16(c[0], c[1], c[2], c[3],
                                av[mf][0], av[mf][1], av[mf][2], av[mf][3],
                                bh[ng][hf], bh[ng][hf + 1]);
                        mma_f16(c[0], c[1], c[2], c[3],
                                av[mf][0], av[mf][1], av[mf][2], av[mf][3],
                                bl[ng][hf], bl[ng][hf + 1]);
                    }
                }
            }
            __syncthreads();
        }

        // epilogue -> SMEM H2 tile
#pragma unroll
        for (int n = 0; n < 4; n++) {
            int cl = warp_n + n * 8 + ec;   // 0..127 local
            int cg = colg + cl;             // 0..255 H2 column
            float wt[4][2];
#pragma unroll
            for (int k = 0; k < 4; k++) {
                wt[k][0] = __ldg(w2 + (size_t)(128 + k) * 256 + cg);
                wt[k][1] = __ldg(w2 + (size_t)(128 + k) * 256 + cg + 1);
            }
            float bb0 = __ldg(b2 + cg), bb1 = __ldg(b2 + cg + 1);
#pragma unroll
            for (int mf = 0; mf < 4; mf++) {
#pragma unroll
                for (int half = 0; half < 2; half++) {
                    int sr = warp_m + mf * 16 + er + half * 8;
                    int g = row0 + sr;
                    if (g >= M) continue;
                    float4 a4 = af[mf][half];
                    float t0 = a4.x * wt[0][0] + a4.y * wt[1][0] + a4.z * wt[2][0] + a4.w * wt[3][0];
                    float t1 = a4.x * wt[0][1] + a4.y * wt[1][1] + a4.z * wt[2][1] + a4.w * wt[3][1];
                    float v0 = fmaxf(acc[mf][n][half * 2 + 0] + bb0 + t0, 0.f);
                    float v1 = fmaxf(acc[mf][n][half * 2 + 1] + bb1 + t1, 0.f);
                    *(__half2*)(smH2 + (size_t)sr * H2S_STRIDE + cg) = __floats2half2_rn(v0, v1);
                }
            }
        }
        __syncthreads();  // H2 writes done before next pass staging / phase 2
    }

    // ======================= phase 2: Z tile =============================
    for (int ns = 0; ns < 4; ns++) {
        const int col0z = ns * 128;
#pragma unroll
        for (int i = 0; i < 4; i++)
#pragma unroll
            for (int j = 0; j < 4; j++)
#pragma unroll
                for (int q = 0; q < 4; q++) acc[i][j][q] = 0.f;

        auto stage2 = [&](int kt, int buf) {
            const int k0 = kt * 32;
            char* base = sm + buf * ZS_STAGE;
#pragma unroll
            for (int it = 0; it < 2; it++) {
                int row = st_row + it * 64;
                size_t gb = (size_t)(col0z + row) * 256 + k0 + st_c8;
                uint32_t so = (uint32_t)(row * ZS_STRIDE + st_c8) * 2;
                *(uint4*)(base + 1 * ZS_TBYTES + so) = *(const uint4*)(B3hi + gb);
                *(uint4*)(base + 2 * ZS_TBYTES + so) = *(const uint4*)(B3lo + gb);
            }
        };

        stage2(0, 0);
        __syncthreads();
        for (int kt = 0; kt < 8; kt++) {
            if (kt < 7) stage2(kt + 1, (kt + 1) & 1);
            const uint32_t bbase = sb + (kt & 1) * ZS_STAGE + 1 * ZS_TBYTES;
#pragma unroll
            for (int ks = 0; ks < 2; ks++) {
                const int kl = ks * 16;
                uint32_t av[4][4];
#pragma unroll
                for (int mf = 0; mf < 4; mf++) {
                    uint32_t ao = sbH2 +
                        (uint32_t)((warp_m + mf * 16 + a_row_l) * H2S_STRIDE + kt * 32 + kl + a_col_l) * 2;
                    ldsm_x4(av[mf][0], av[mf][1], av[mf][2], av[mf][3], ao);
                }
                uint32_t bh[2][4], bl[2][4];
#pragma unroll
                for (int ng = 0; ng < 2; ng++) {
                    uint32_t bo = bbase +
                        (uint32_t)((warp_n + ng * 16 + b_n_l + b_row_l) * ZS_STRIDE + kl + b_k_l) * 2;
                    ldsm_x4(bh[ng][0], bh[ng][1], bh[ng][2], bh[ng][3], bo);
                    ldsm_x4(bl[ng][0], bl[ng][1], bl[ng][2], bl[ng][3], bo + ZS_TBYTES);
                }
#pragma unroll
                for (int mf = 0; mf < 4; mf++) {
#pragma unroll
                    for (int n = 0; n < 4; n++) {
                        const int ng = n >> 1, hf = (n & 1) * 2;
                        float* c = acc[mf][n];
                        mma_f16(c[0], c[1], c[2], c[3],
                                av[mf][0], av[mf][1], av[mf][2], av[mf][3],
                                bh[ng][hf], bh[ng][hf + 1]);
                        mma_f16(c[0], c[1], c[2], c[3],
                                av[mf][0], av[mf][1], av[mf][2], av[mf][3],
                                bl[ng][hf], bl[ng][hf + 1]);
                    }
                }
            }
            __syncthreads();
        }

        // epilogue -> Zh global
#pragma unroll
        for (int mf = 0; mf < 4; mf++) {
            int r0g = row0 + warp_m + mf * 16 + er;
            int r1g = r0g + 8;
#pragma unroll
            for (int n = 0; n < 4; n++) {
                int cg = col0z + warp_n + n * 8 + ec;
                if (r0g < M)
                    *(__half2*)(Zh + (size_t)r0g * 512 + cg) = __floats2half2_rn(acc[mf][n][0], acc[mf][n][1]);
                if (r1g < M)
                    *(__half2*)(Zh + (size_t)r1g * 512 + cg) = __floats2half2_rn(acc[mf][n][2], acc[mf][n][3]);
            }
        }
    }
}

// ----------- K6: unpool (warp-per-point, fp16 Z gather, fused h4) ----------
__global__ __launch_bounds__(256)
void unpool_kernel(const __half* __restrict__ Zh, const float* __restrict__ x3,
                   const int* __restrict__ bcols, const float* __restrict__ bvals,
                   const float* __restrict__ w3, const float* __restrict__ b3,
                   const float* __restrict__ w4, const float* __restrict__ b4,
                   float* __restrict__ out_h3, float* __restrict__ out_cat,
                   float* __restrict__ logits, float* __restrict__ h4out) {
    int t = blockIdx.x * blockDim.x + threadIdx.x;
    int i = t >> 5, lane = t & 31;
    if (i >= N_POINTS) return;
    int c = __ldg(bcols + i);
    float s = __ldg(bvals + i);
    float4 xv = *(const float4*)(x3 + (size_t)i * 4);
    const float* w3t = w3 + (size_t)256 * 512;

    float4 h4acc = make_float4(0.f, 0.f, 0.f, 0.f);
#pragma unroll
    for (int q = 0; q < 4; q++) {
        int n = q * 128 + lane * 4;
        uint2 zu = __ldg((const uint2*)(Zh + (size_t)c * 512 + n));
        float2 z01 = __half22float2(*reinterpret_cast<__half2*>(&zu.x));
        float2 z23 = __half22float2(*reinterpret_cast<__half2*>(&zu.y));
        float4 u0 = __ldg((const float4*)(w3t + 0 * 512 + n));
        float4 u1 = __ldg((const float4*)(w3t + 1 * 512 + n));
        float4 u2 = __ldg((const float4*)(w3t + 2 * 512 + n));
        float4 u3 = __ldg((const float4*)(w3t + 3 * 512 + n));
        float4 bb = __ldg((const float4*)(b3 + n));
        float4 v;
        v.x = fmaxf(s * z01.x + xv.x * u0.x + xv.y * u1.x + xv.z * u2.x + xv.w * u3.x + bb.x, 0.f);
        v.y = fmaxf(s * z01.y + xv.x * u0.y + xv.y * u1.y + xv.z * u2.y + xv.w * u3.y + bb.y, 0.f);
        v.z = fmaxf(s * z23.x + xv.x * u0.z + xv.y * u1.z + xv.z * u2.z + xv.w * u3.z + bb.z, 0.f);
        v.w = fmaxf(s * z23.y + xv.x * u0.w + xv.y * u1.w + xv.z * u2.w + xv.w * u3.w + bb.w, 0.f);
        stcs4(out_h3 + (size_t)i * 512 + n, v);
        stcs4(out_cat + (size_t)i * 516 + n, v);
        float4 r0 = __ldg((const float4*)(w4 + (size_t)(n + 0) * 4));
        float4 r1 = __ldg((const float4*)(w4 + (size_t)(n + 1) * 4));
        float4 r2 = __ldg((const float4*)(w4 + (size_t)(n + 2) * 4));
        float4 r3 = __ldg((const float4*)(w4 + (size_t)(n + 3) * 4));
        h4acc.x += v.x * r0.x + v.y * r1.x + v.z * r2.x + v.w * r3.x;
        h4acc.y += v.x * r0.y + v.y * r1.y + v.z * r2.y + v.w * r3.y;
        h4acc.z += v.x * r0.z + v.y * r1.z + v.z * r2.z + v.w * r3.z;
        h4acc.w += v.x * r0.w + v.y * r1.w + v.z * r2.w + v.w * r3.w;
    }
#pragma unroll
    for (int off = 16; off > 0; off >>= 1) {
        h4acc.x += __shfl_xor_sync(0xFFFFFFFFu, h4acc.x, off);
        h4acc.y += __shfl_xor_sync(0xFFFFFFFFu, h4acc.y, off);
        h4acc.z += __shfl_xor_sync(0xFFFFFFFFu, h4acc.z, off);
        h4acc.w += __shfl_xor_sync(0xFFFFFFFFu, h4acc.w, off);
    }
    if (lane == 0) {
        float4 t0 = __ldg((const float4*)(w4 + (size_t)512 * 4));
        float4 t1 = __ldg((const float4*)(w4 + (size_t)513 * 4));
        float4 t2 = __ldg((const float4*)(w4 + (size_t)514 * 4));
        float4 t3 = __ldg((const float4*)(w4 + (size_t)515 * 4));
        float4 bb = __ldg((const float4*)b4);
        h4acc.x += xv.x * t0.x + xv.y * t1.x + xv.z * t2.x + xv.w * t3.x + bb.x;
        h4acc.y += xv.x * t0.y + xv.y * t1.y + xv.z * t2.y + xv.w * t3.y + bb.y;
        h4acc.z += xv.x * t0.z + xv.y * t1.z + xv.z * t2.z + xv.w * t3.z + bb.z;
        h4acc.w += xv.x * t0.w + xv.y * t1.w + xv.z * t2.w + xv.w * t3.w + bb.w;
        stcs4(logits + (size_t)i * 4, h4acc);
        stcs4(h4out + (size_t)i * 4, h4acc);
    } else if (lane == 1) {
        stcs4(out_cat + (size_t)i * 516 + 512, xv);
    }
}

// ---------------------------------------------------------------------------
extern "C" void kernel_launch(void* const* d_in, const int* in_sizes, int n_in,
                              void* d_out, int out_size) {
    const float* feature  = (const float*)d_in[0];
    const float* x3       = (const float*)d_in[1];
    const int*   adj_rows = (const int*)d_in[2];
    const int*   adj_cols = (const int*)d_in[3];
    const float* adj_vals = (const float*)d_in[4];
    // d_in[5] = bing_rows (arange, unused)
    const int*   bing_cols = (const int*)d_in[6];
    const float* bing_vals = (const float*)d_in[7];
    const float* w1 = (const float*)d_in[8];
    const float* b1 = (const float*)d_in[9];
    const float* w2 = (const float*)d_in[10];
    const float* b2 = (const float*)d_in[11];
    const float* w3 = (const float*)d_in[12];
    const float* b3 = (const float*)d_in[13];
    const float* w4 = (const float*)d_in[14];
    const float* b4 = (const float*)d_in[15];
    float* out = (float*)d_out;
    const int nE = in_sizes[2];
    const int EB = (nE + 255) / 256;

    float *AF;
    __half *Zh, *h1h, *AH1h, *Wt2hi, *Wt2lo, *Wthi, *Wtlo;
    int *cnt, *rowptr, *fill, *bsum;
    int2 *edge;
    cudaGetSymbolAddress((void**)&AF, g_AF);
    cudaGetSymbolAddress((void**)&Zh, g_Zh);
    cudaGetSymbolAddress((void**)&cnt, g_cnt);
    cudaGetSymbolAddress((void**)&rowptr, g_rowptr);
    cudaGetSymbolAddress((void**)&fill, g_fill);
    cudaGetSymbolAddress((void**)&edge, g_edge);
    cudaGetSymbolAddress((void**)&bsum, g_bsum);
    cudaGetSymbolAddress((void**)&h1h, g_h1h);
    cudaGetSymbolAddress((void**)&AH1h, g_AH1h);
    cudaGetSymbolAddress((void**)&Wt2hi, g_Wt2hi);
    cudaGetSymbolAddress((void**)&Wt2lo, g_Wt2lo);
    cudaGetSymbolAddress((void**)&Wthi, g_Wthi);
    cudaGetSymbolAddress((void**)&Wtlo, g_Wtlo);

    cudaFuncSetAttribute(gemm25_mma, cudaFuncAttributeMaxDynamicSharedMemorySize, FUSED_SMEM);

    cudaMemsetAsync(AF, 0, (size_t)N_POOL * 4 * sizeof(float));
    cudaMemsetAsync(cnt, 0, (size_t)N_POOL * sizeof(int));

    // CSR build (multi-block scan; scan_final also seeds fill)
    count_kernel<<<EB, 256>>>(adj_rows, cnt, nE);
    scan_reduce<<<SCAN_B, 1024>>>(cnt, bsum, N_POOL);
    scan_tops<<<1, 128>>>(bsum, rowptr + N_POOL, SCAN_B);
    scan_final<<<SCAN_B, 1024>>>(cnt, bsum, rowptr, fill, N_POOL);
    // edge scatter (packed) + fused spmm4 (AF)
    build_kernel<<<EB, 256>>>(adj_rows, adj_cols, adj_vals, fill, edge, feature, AF, nE);

    // weight converts (independent)
    convert_w3_kernel<<<(512 * 256 + 255) / 256, 256>>>(w3, Wthi, Wtlo);
    convert_w2_kernel<<<(256 * 128 + 255) / 256, 256>>>(w2, Wt2hi, Wt2lo);

    // K2: h1cat -> d_out H1 region + dense fp16 copy
    h1_kernel<<<N_POOL, 128>>>(AF, feature, w1, b1, out + OFF_H1, h1h);

    // K3: AH1 = csr-spmm(adj, h1h) -> fp16
    spmm128_csr<<<(N_POOL * 32 + 255) / 256, 256>>>(rowptr, edge, h1h, AH1h);

    // K4+K5 fused: h2 (smem) -> Z (fp16 global)
    gemm25_mma<<<M_PAD / 128, 256, FUSED_SMEM>>>(AH1h, Wt2hi, Wt2lo, Wthi, Wtlo,
                                                 AF, w2, b2, Zh, N_POOL);

    // K6: unpool (warp-per-point, fp16 Z gather)
    unpool_kernel<<<(N_POINTS * 32 + 255) / 256, 256>>>(Zh, x3, bing_cols, bing_vals,
                                                        w3, b3, w4, b4,
                                                        out + OFF_H2OUT, out + OFF_H3CAT,
                                                        out + OFF_LOGITS, out + OFF_H4);
}

// round 16
// speedup vs baseline: 1.0582x; 1.0582x over previous
#include <cuda_runtime.h>
#include <cuda_bf16.h>
#include <cuda_fp16.h>
#include <cstddef>
#include <cstdint>

// ---------------------------------------------------------------------------
// GcnNet restructured (round 16 = R14 architecture, micro-polish):
//   CSR  = counting-sort of adj edges by row (multi-block scan); spmm4 fused
//   h1   = relu(AF @ w1 + b1); h1cat -> d_out (.cs); PLUS dense fp16 copy h1h
//   AH1  = csr-spmm(adj, h1h) -> fp16 single
//   h2   = relu(AH1 @ w2[:128] + AF @ w2[128:] + b2) via fp16 mma (B hi/lo)
//   Z    = h2 @ w3[0:256] via fp16 mma (B hi/lo) -> fp16 (L2-resident)
//   h3[i]= relu(bv[i]*Z[bc[i]] + x3[i] @ w3[256:260] + b3) (warp-per-point
//          unpool, fused h4, streaming stores)
// Output layout (floats): [logits | h1cat | h2_out(=h3) | h3_cat | h4]
// ---------------------------------------------------------------------------

#define N_POOL   100000
#define N_POINTS 400000
#define N_EDGES  3200000
#define M_PAD    100096   // 782 * 128
#define SCAN_B   98       // ceil(100000/1024)

static const size_t OFF_LOGITS = 0;
static const size_t OFF_H1     = (size_t)N_POINTS * 4;
static const size_t OFF_H2OUT  = OFF_H1 + (size_t)N_POOL * 132;
static const size_t OFF_H3CAT  = OFF_H2OUT + (size_t)N_POINTS * 512;
static const size_t OFF_H4     = OFF_H3CAT + (size_t)N_POINTS * 516;

// scratch (no cudaMalloc allowed). __device__ globals are zero-initialized.
__device__ float g_AF[(size_t)N_POOL * 4];
__device__ int   g_cnt[N_POOL];
__device__ int   g_rowptr[N_POOL + 1];
__device__ int   g_fill[N_POOL];
__device__ int   g_bsum[SCAN_B];
__device__ int2  g_edge[N_EDGES];   // (col, val-as-int)
__device__ __half g_h1h[(size_t)N_POOL * 128];   // dense fp16 gather copy
__device__ __half g_AH1h[(size_t)M_PAD * 128];   // fp16 single
__device__ __half g_H2h[(size_t)M_PAD * 256];    // fp16 single
__device__ __half g_Wt2hi[(size_t)256 * 128];    // w2[0:128]^T K-contig fp16 hi
__device__ __half g_Wt2lo[(size_t)256 * 128];    // fp16 lo
__device__ __half g_Wthi[(size_t)512 * 256];     // w3[0:256]^T K-contig fp16 hi
__device__ __half g_Wtlo[(size_t)512 * 256];     // fp16 lo
__device__ __half g_Zh[(size_t)N_POOL * 512];    // Z in fp16 (L2-resident)

// ------------------------------ helpers ------------------------------------
__device__ __forceinline__ uint32_t smem_to_u32(const void* p) {
    uint32_t a;
    asm("{ .reg .u64 t; cvta.to.shared.u64 t, %1; cvt.u32.u64 %0, t; }" : "=r"(a) : "l"(p));
    return a;
}
__device__ __forceinline__ void ldsm_x4(uint32_t& r0, uint32_t& r1, uint32_t& r2, uint32_t& r3,
                                        uint32_t addr) {
    asm volatile("ldmatrix.sync.aligned.m8n8.x4.shared.b16 {%0,%1,%2,%3}, [%4];"
                 : "=r"(r0), "=r"(r1), "=r"(r2), "=r"(r3) : "r"(addr));
}
__device__ __forceinline__ void mma_f16(float& c0, float& c1, float& c2, float& c3,
                                        uint32_t a0, uint32_t a1, uint32_t a2, uint32_t a3,
                                        uint32_t b0, uint32_t b1) {
    asm volatile("mma.sync.aligned.m16n8k16.row.col.f32.f16.f16.f32 "
                 "{%0,%1,%2,%3}, {%4,%5,%6,%7}, {%8,%9}, {%0,%1,%2,%3};"
                 : "+f"(c0), "+f"(c1), "+f"(c2), "+f"(c3)
                 : "r"(a0), "r"(a1), "r"(a2), "r"(a3), "r"(b0), "r"(b1));
}
__device__ __forceinline__ void red_add_v4(float* p, float a, float b, float c, float d) {
    asm volatile("red.global.add.v4.f32 [%0], {%1, %2, %3, %4};"
                 :: "l"(p), "f"(a), "f"(b), "f"(c), "f"(d) : "memory");
}
__device__ __forceinline__ void stcs4(float* p, float4 v) {
    asm volatile("st.global.cs.v4.f32 [%0], {%1, %2, %3, %4};"
                 :: "l"(p), "f"(v.x), "f"(v.y), "f"(v.z), "f"(v.w) : "memory");
}
__device__ __forceinline__ void stcs1(float* p, float v) {
    asm volatile("st.global.cs.f32 [%0], %1;" :: "l"(p), "f"(v) : "memory");
}

// --------------------------- CSR build -------------------------------------
__global__ void count_kernel(const int* __restrict__ keys, int* __restrict__ cnt, int n) {
    int e = blockIdx.x * blockDim.x + threadIdx.x;
    if (e < n) atomicAdd(cnt + __ldg(keys + e), 1);
}

__global__ void scan_reduce(const int* __restrict__ cnt, int* __restrict__ bsum, int n) {
    __shared__ int s[32];
    int tid = threadIdx.x, lane = tid & 31, wid = tid >> 5;
    int i = blockIdx.x * 1024 + tid;
    int v = (i < n) ? cnt[i] : 0;
#pragma unroll
    for (int off = 16; off > 0; off >>= 1) v += __shfl_down_sync(0xFFFFFFFFu, v, off);
    if (lane == 0) s[wid] = v;
    __syncthreads();
    if (wid == 0) {
        int x = s[lane];
#pragma unroll
        for (int off = 16; off > 0; off >>= 1) x += __shfl_down_sync(0xFFFFFFFFu, x, off);
        if (lane == 0) bsum[blockIdx.x] = x;
    }
}

__global__ void scan_tops(int* __restrict__ bsum, int* __restrict__ rowptr_last, int nb) {
    __shared__ int s[128];
    int t = threadIdx.x;  // 128 threads
    int v = (t < nb) ? bsum[t] : 0;
    s[t] = v;
    __syncthreads();
    for (int off = 1; off < 128; off <<= 1) {
        int x = (t >= off) ? s[t - off] : 0;
        __syncthreads();
        s[t] += x;
        __syncthreads();
    }
    if (t < nb) bsum[t] = s[t] - v;             // exclusive
    if (t == nb - 1) *rowptr_last = s[t];       // total -> rowptr[N_POOL]
}

__global__ void scan_final(const int* __restrict__ cnt, const int* __restrict__ bsum,
                           int* __restrict__ rowptr, int* __restrict__ fill, int n) {
    __shared__ int ws[32];
    int tid = threadIdx.x, lane = tid & 31, wid = tid >> 5;
    int i = blockIdx.x * 1024 + tid;
    int v = (i < n) ? cnt[i] : 0;
    int inc = v;
#pragma unroll
    for (int off = 1; off < 32; off <<= 1) {
        int x = __shfl_up_sync(0xFFFFFFFFu, inc, off);
        if (lane >= off) inc += x;
    }
    if (lane == 31) ws[wid] = inc;
    __syncthreads();
    if (wid == 0) {
        int x = ws[lane];
#pragma unroll
        for (int off = 1; off < 32; off <<= 1) {
            int y = __shfl_up_sync(0xFFFFFFFFu, x, off);
            if (lane >= off) x += y;
        }
        ws[lane] = x;
    }
    __syncthreads();
    int woff = (wid > 0) ? ws[wid - 1] : 0;
    if (i < n) {
        int p = inc - v + woff + __ldg(bsum + blockIdx.x);
        rowptr[i] = p;
        fill[i] = p;
    }
}

// edge scatter (packed int2) fused with spmm4 (AF = A @ feature)
__global__ void build_kernel(const int* __restrict__ rows, const int* __restrict__ cols,
                             const float* __restrict__ vals, int* __restrict__ fill,
                             int2* __restrict__ edge,
                             const float* __restrict__ F, float* __restrict__ AF, int nE) {
    int e = blockIdx.x * blockDim.x + threadIdx.x;
    if (e >= nE) return;
    int r = __ldg(rows + e);
    int c = __ldg(cols + e);
    float v = __ldg(vals + e);
    int pos = atomicAdd(fill + r, 1);
    edge[pos] = make_int2(c, __float_as_int(v));
    float4 f = *(const float4*)(F + (size_t)c * 4);
    red_add_v4(AF + (size_t)r * 4, v * f.x, v * f.y, v * f.z, v * f.w);
}

// ------------- K2: h1 = relu(AF@w1+b1) -> h1cat (.cs) + fp16 copy ----------
__global__ void h1_kernel(const float* __restrict__ AF, const float* __restrict__ F,
                          const float* __restrict__ w1, const float* __restrict__ b1,
                          float* __restrict__ out_h1, __half* __restrict__ h1h) {
    int r = blockIdx.x;
    int j = threadIdx.x;  // 128
    float4 a = *(const float4*)(AF + (size_t)r * 4);
    float s = __ldg(b1 + j)
            + a.x * __ldg(w1 + j)
            + a.y * __ldg(w1 + 128 + j)
            + a.z * __ldg(w1 + 256 + j)
            + a.w * __ldg(w1 + 384 + j);
    s = fmaxf(s, 0.f);
    float* row = out_h1 + (size_t)r * 132;
    stcs1(row + j, s);                       // final output; never re-read
    h1h[(size_t)r * 128 + j] = __float2half(s);
    if (j < 4) stcs1(row + 128 + j, F[(size_t)r * 4 + j]);
}

// ----------------- K3: AH1 = csr-spmm(adj, h1h) -> fp16 single -------------
__global__ __launch_bounds__(256)
void spmm128_csr(const int* __restrict__ rowptr, const int2* __restrict__ edge,
                 const __half* __restrict__ h1h, __half* __restrict__ AH1h) {
    int r = (blockIdx.x * blockDim.x + threadIdx.x) >> 5;
    if (r >= N_POOL) return;
    int lane = threadIdx.x & 31;
    int start = __ldg(rowptr + r), end = __ldg(rowptr + r + 1);
    float4 acc = make_float4(0.f, 0.f, 0.f, 0.f);
    const int loff = lane * 4;
    for (int base = start; base < end; base += 32) {
        int n = min(32, end - base);
        int2 ev = make_int2(0, 0);
        if (lane < n) ev = __ldg(edge + base + lane);
        int j = 0;
        for (; j + 8 <= n; j += 8) {
            int cc[8]; float vv[8]; uint2 uu[8];
#pragma unroll
            for (int q = 0; q < 8; q++) {
                cc[q] = __shfl_sync(0xFFFFFFFFu, ev.x, j + q);
                vv[q] = __int_as_float(__shfl_sync(0xFFFFFFFFu, ev.y, j + q));
            }
#pragma unroll
            for (int q = 0; q < 8; q++)
                uu[q] = *(const uint2*)(h1h + (size_t)cc[q] * 128 + loff);
#pragma unroll
            for (int q = 0; q < 8; q++) {
                float2 f01 = __half22float2(*reinterpret_cast<__half2*>(&uu[q].x));
                float2 f23 = __half22float2(*reinterpret_cast<__half2*>(&uu[q].y));
                acc.x += vv[q] * f01.x;
                acc.y += vv[q] * f01.y;
                acc.z += vv[q] * f23.x;
                acc.w += vv[q] * f23.y;
            }
        }
        for (; j < n; j++) {
            int cj = __shfl_sync(0xFFFFFFFFu, ev.x, j);
            float vj = __int_as_float(__shfl_sync(0xFFFFFFFFu, ev.y, j));
            uint2 u = *(const uint2*)(h1h + (size_t)cj * 128 + loff);
            float2 f01 = __half22float2(*reinterpret_cast<__half2*>(&u.x));
            float2 f23 = __half22float2(*reinterpret_cast<__half2*>(&u.y));
            acc.x += vj * f01.x; acc.y += vj * f01.y;
            acc.z += vj * f23.x; acc.w += vj * f23.y;
        }
    }
    union { __half2 h2[2]; uint2 u; } p;
    p.h2[0] = __floats2half2_rn(acc.x, acc.y);
    p.h2[1] = __floats2half2_rn(acc.z, acc.w);
    *(uint2*)(AH1h + (size_t)r * 128 + loff) = p.u;
}

// ------------- converts: w2^T and w3^T to fp16 hi/lo (one launch) ----------
__global__ void convert_w_kernel(const float* __restrict__ w2, const float* __restrict__ w3,
                                 __half* __restrict__ w2hi, __half* __restrict__ w2lo,
                                 __half* __restrict__ w3hi, __half* __restrict__ w3lo) {
    int t = blockIdx.x * blockDim.x + threadIdx.x;
    if (t < 256 * 128) {
        int n = t >> 7, k = t & 127;
        float v = __ldg(w2 + (size_t)k * 256 + n);
        __half h = __float2half_rn(v);
        w2hi[t] = h;
        w2lo[t] = __float2half_rn(v - __half2float(h));
    }
    int t3 = t - 256 * 128;
    if (t3 >= 0 && t3 < 512 * 256) {
        int n = t3 >> 8, k = t3 & 255;
        float v = __ldg(w3 + (size_t)k * 512 + n);
        __half h = __float2half_rn(v);
        w3hi[t3] = h;
        w3lo[t3] = __float2half_rn(v - __half2float(h));
    }
}

// ===========================================================================
// fp16 mma.sync GEMM bodies: block 128x128, 8 warps (2x4), warp 64x32, BK=32
// 3 smem tensors per stage: A, Bhi, Blo (each 128 x 40 halves = 10240 B)
// ===========================================================================
#define ZS_STRIDE 40
#define ZS_TBYTES (128 * ZS_STRIDE * 2)
#define ZS_STAGE  (3 * ZS_TBYTES)
#define ZS_TOTAL  (2 * ZS_STAGE)   // 61440

// --------------------------- K4: gemm2 via fp16 mma ------------------------
__global__ __launch_bounds__(256)
void gemm2_mma(const __half* __restrict__ A, const __half* __restrict__ Bhi,
               const __half* __restrict__ Blo,
               const float* __restrict__ AF, const float* __restrict__ w2,
               const float* __restrict__ b2, __half* __restrict__ H2h, int M) {
    extern __shared__ char sm[];
    const int tid = threadIdx.x;
    const int lane = tid & 31, wid = tid >> 5;
    const int warp_m = (wid & 1) * 64;
    const int warp_n = (wid >> 1) * 32;
    const int row0 = blockIdx.y * 128;
    const int col0 = blockIdx.x * 128;
    const uint32_t sb = smem_to_u32(sm);

    const int st_row = tid >> 2;
    const int st_c8  = (tid & 3) << 3;

    auto stage = [&](int kt, int buf) {
        const int k0 = kt * 32;
        char* base = sm + buf * ZS_STAGE;
#pragma unroll
        for (int it = 0; it < 2; it++) {
            int row = st_row + it * 64;
            size_t ga = (size_t)(row0 + row) * 128 + k0 + st_c8;
            size_t gb = (size_t)(col0 + row) * 128 + k0 + st_c8;
            uint32_t so = (uint32_t)(row * ZS_STRIDE + st_c8) * 2;
            *(uint4*)(base + 0 * ZS_TBYTES + so) = *(const uint4*)(A + ga);
            *(uint4*)(base + 1 * ZS_TBYTES + so) = *(const uint4*)(Bhi + gb);
            *(uint4*)(base + 2 * ZS_TBYTES + so) = *(const uint4*)(Blo + gb);
        }
    };

    float acc[4][4][4];
#pragma unroll
    for (int i = 0; i < 4; i++)
#pragma unroll
        for (int j = 0; j < 4; j++)
#pragma unroll
            for (int q = 0; q < 4; q++) acc[i][j][q] = 0.f;

    const int a_row_l = (lane & 7) + ((lane >> 3) & 1) * 8;
    const int a_col_l = (lane >> 4) * 8;
    const int b_row_l = lane & 7;
    const int b_n_l   = (lane >> 4) * 8;
    const int b_k_l   = ((lane >> 3) & 1) * 8;

    stage(0, 0);
    __syncthreads();

    for (int kt = 0; kt < 4; kt++) {
        if (kt < 3) stage(kt + 1, (kt + 1) & 1);
        const uint32_t abase = sb + (kt & 1) * ZS_STAGE;
        const uint32_t bbase = abase + 1 * ZS_TBYTES;
#pragma unroll
        for (int ks = 0; ks < 2; ks++) {
            const int kl = ks * 16;
            uint32_t av[4][4];
#pragma unroll
            for (int mf = 0; mf < 4; mf++) {
                uint32_t ao = abase +
                    (uint32_t)((warp_m + mf * 16 + a_row_l) * ZS_STRIDE + kl + a_col_l) * 2;
                ldsm_x4(av[mf][0], av[mf][1], av[mf][2], av[mf][3], ao);
            }
            uint32_t bh[2][4], bl[2][4];
#pragma unroll
            for (int ng = 0; ng < 2; ng++) {
                uint32_t bo = bbase +
                    (uint32_t)((warp_n + ng * 16 + b_n_l + b_row_l) * ZS_STRIDE + kl + b_k_l) * 2;
                ldsm_x4(bh[ng][0], bh[ng][1], bh[ng][2], bh[ng][3], bo);
                ldsm_x4(bl[ng][0], bl[ng][1], bl[ng][2], bl[ng][3], bo + ZS_TBYTES);
            }
#pragma unroll
            for (int mf = 0; mf < 4; mf++) {
#pragma unroll
                for (int n = 0; n < 4; n++) {
                    const int ng = n >> 1, hf = (n & 1) * 2;
                    float* c = acc[mf][n];
                    mma_f16(c[0], c[1], c[2], c[3],
                            av[mf][0], av[mf][1], av[mf][2], av[mf][3],
                            bh[ng][hf], bh[ng][hf + 1]);
                    mma_f16(c[0], c[1], c[2], c[3],
                            av[mf][0], av[mf][1], av[mf][2], av[mf][3],
                            bl[ng][hf], bl[ng][hf + 1]);
                }
            }
        }
        __syncthreads();
    }

    // epilogue: + AF @ w2[128:132] + b2, relu, fp16 store
    const int er = lane >> 2, ec = (lane & 3) * 2;
    float4 af[4][2];
#pragma unroll
    for (int mf = 0; mf < 4; mf++) {
        int r0g = row0 + warp_m + mf * 16 + er;
        af[mf][0] = (r0g < M)     ? *(const float4*)(AF + (size_t)r0g * 4)       : make_float4(0, 0, 0, 0);
        af[mf][1] = (r0g + 8 < M) ? *(const float4*)(AF + (size_t)(r0g + 8) * 4) : make_float4(0, 0, 0, 0);
    }
#pragma unroll
    for (int n = 0; n < 4; n++) {
        int cg = col0 + warp_n + n * 8 + ec;
        float wt[4][2];
#pragma unroll
        for (int k = 0; k < 4; k++) {
            wt[k][0] = __ldg(w2 + (size_t)(128 + k) * 256 + cg);
            wt[k][1] = __ldg(w2 + (size_t)(128 + k) * 256 + cg + 1);
        }
        float bb0 = __ldg(b2 + cg), bb1 = __ldg(b2 + cg + 1);
#pragma unroll
        for (int mf = 0; mf < 4; mf++) {
#pragma unroll
            for (int half = 0; half < 2; half++) {
                int g = row0 + warp_m + mf * 16 + er + half * 8;
                if (g >= M) continue;
                float4 a4 = af[mf][half];
                float t0 = a4.x * wt[0][0] + a4.y * wt[1][0] + a4.z * wt[2][0] + a4.w * wt[3][0];
                float t1 = a4.x * wt[0][1] + a4.y * wt[1][1] + a4.z * wt[2][1] + a4.w * wt[3][1];
                float v0 = fmaxf(acc[mf][n][half * 2 + 0] + bb0 + t0, 0.f);
                float v1 = fmaxf(acc[mf][n][half * 2 + 1] + bb1 + t1, 0.f);
                *(__half2*)(H2h + (size_t)g * 256 + cg) = __floats2half2_rn(v0, v1);
            }
        }
    }
}

// --------------------------- K5: Z = h2 @ w3a (fp16 mma) -> fp16 -----------
__global__ __launch_bounds__(256)
void gemmZ_mma(const __half* __restrict__ A, const __half* __restrict__ Bhi,
               const __half* __restrict__ Blo, __half* __restrict__ Zh, int M) {
    extern __shared__ char sm[];
    const int tid = threadIdx.x;
    const int lane = tid & 31, wid = tid >> 5;
    const int warp_m = (wid & 1) * 64;
    const int warp_n = (wid >> 1) * 32;
    const int row0 = blockIdx.y * 128;
    const int col0 = blockIdx.x * 128;
    const uint32_t sb = smem_to_u32(sm);

    const int st_row = tid >> 2;
    const int st_c8  = (tid & 3) << 3;

    auto stage = [&](int kt, int buf) {
        const int k0 = kt * 32;
        char* base = sm + buf * ZS_STAGE;
#pragma unroll
        for (int it = 0; it < 2; it++) {
            int row = st_row + it * 64;
            size_t ga = (size_t)(row0 + row) * 256 + k0 + st_c8;
            size_t gb = (size_t)(col0 + row) * 256 + k0 + st_c8;
            uint32_t so = (uint32_t)(row * ZS_STRIDE + st_c8) * 2;
            *(uint4*)(base + 0 * ZS_TBYTES + so) = *(const uint4*)(A + ga);
            *(uint4*)(base + 1 * ZS_TBYTES + so) = *(const uint4*)(Bhi + gb);
            *(uint4*)(base + 2 * ZS_TBYTES + so) = *(const uint4*)(Blo + gb);
        }
    };

    float acc[4][4][4];
#pragma unroll
    for (int i = 0; i < 4; i++)
#pragma unroll
        for (int j = 0; j < 4; j++)
#pragma unroll
            for (int q = 0; q < 4; q++) acc[i][j][q] = 0.f;

    const int a_row_l = (lane & 7) + ((lane >> 3) & 1) * 8;
    const int a_col_l = (lane >> 4) * 8;
    const int b_row_l = lane & 7;
    const int b_n_l   = (lane >> 4) * 8;
    const int b_k_l   = ((lane >> 3) & 1) * 8;

    stage(0, 0);
    __syncthreads();

    for (int kt = 0; kt < 8; kt++) {
        if (kt < 7) stage(kt + 1, (kt + 1) & 1);
        const uint32_t abase = sb + (kt & 1) * ZS_STAGE;
        const uint32_t bbase = abase + 1 * ZS_TBYTES;
#pragma unroll
        for (int ks = 0; ks < 2; ks++) {
            const int kl = ks * 16;
            uint32_t av[4][4];
#pragma unroll
            for (int mf = 0; mf < 4; mf++) {
                uint32_t ao = abase +
                    (uint32_t)((warp_m + mf * 16 + a_row_l) * ZS_STRIDE + kl + a_col_l) * 2;
                ldsm_x4(av[mf][0], av[mf][1], av[mf][2], av[mf][3], ao);
            }
            uint32_t bh[2][4], bl[2][4];
#pragma unroll
            for (int ng = 0; ng < 2; ng++) {
                uint32_t bo = bbase +
                    (uint32_t)((warp_n + ng * 16 + b_n_l + b_row_l) * ZS_STRIDE + kl + b_k_l) * 2;
                ldsm_x4(bh[ng][0], bh[ng][1], bh[ng][2], bh[ng][3], bo);
                ldsm_x4(bl[ng][0], bl[ng][1], bl[ng][2], bl[ng][3], bo + ZS_TBYTES);
            }
#pragma unroll
            for (int mf = 0; mf < 4; mf++) {
#pragma unroll
                for (int n = 0; n < 4; n++) {
                    const int ng = n >> 1, hf = (n & 1) * 2;
                    float* c = acc[mf][n];
                    mma_f16(c[0], c[1], c[2], c[3],
                            av[mf][0], av[mf][1], av[mf][2], av[mf][3],
                            bh[ng][hf], bh[ng][hf + 1]);
                    mma_f16(c[0], c[1], c[2], c[3],
                            av[mf][0], av[mf][1], av[mf][2], av[mf][3],
                            bl[ng][hf], bl[ng][hf + 1]);
                }
            }
        }
        __syncthreads();
    }

    const int er = lane >> 2, ec = (lane & 3) * 2;
#pragma unroll
    for (int mf = 0; mf < 4; mf++) {
        int r0g = row0 + warp_m + mf * 16 + er;
        int r1g = r0g + 8;
#pragma unroll
        for (int n = 0; n < 4; n++) {
            int cg = col0 + warp_n + n * 8 + ec;
            if (r0g < M)
                *(__half2*)(Zh + (size_t)r0g * 512 + cg) = __floats2half2_rn(acc[mf][n][0], acc[mf][n][1]);
            if (r1g < M)
                *(__half2*)(Zh + (size_t)r1g * 512 + cg) = __floats2half2_rn(acc[mf][n][2], acc[mf][n][3]);
        }
    }
}

// ----------- K6: unpool (warp-per-point, fp16 Z gather, fused h4) ----------
__global__ __launch_bounds__(256)
void unpool_kernel(const __half* __restrict__ Zh, const float* __restrict__ x3,
                   const int* __restrict__ bcols, const float* __restrict__ bvals,
                   const float* __restrict__ w3, const float* __restrict__ b3,
                   const float* __restrict__ w4, const float* __restrict__ b4,
                   float* __restrict__ out_h3, float* __restrict__ out_cat,
                   float* __restrict__ logits, float* __restrict__ h4out) {
    int t = blockIdx.x * blockDim.x + threadIdx.x;
    int i = t >> 5, lane = t & 31;
    if (i >= N_POINTS) return;
    int c = __ldg(bcols + i);
    float s = __ldg(bvals + i);
    float4 xv = *(const float4*)(x3 + (size_t)i * 4);
    const float* w3t = w3 + (size_t)256 * 512;

    float4 h4acc = make_float4(0.f, 0.f, 0.f, 0.f);
#pragma unroll
    for (int q = 0; q < 4; q++) {
        int n = q * 128 + lane * 4;
        uint2 zu = __ldg((const uint2*)(Zh + (size_t)c * 512 + n));
        float2 z01 = __half22float2(*reinterpret_cast<__half2*>(&zu.x));
        float2 z23 = __half22float2(*reinterpret_cast<__half2*>(&zu.y));
        float4 u0 = __ldg((const float4*)(w3t + 0 * 512 + n));
        float4 u1 = __ldg((const float4*)(w3t + 1 * 512 + n));
        float4 u2 = __ldg((const float4*)(w3t + 2 * 512 + n));
        float4 u3 = __ldg((const float4*)(w3t + 3 * 512 + n));
        float4 bb = __ldg((const float4*)(b3 + n));
        float4 v;
        v.x = fmaxf(s * z01.x + xv.x * u0.x + xv.y * u1.x + xv.z * u2.x + xv.w * u3.x + bb.x, 0.f);
        v.y = fmaxf(s * z01.y + xv.x * u0.y + xv.y * u1.y + xv.z * u2.y + xv.w * u3.y + bb.y, 0.f);
        v.z = fmaxf(s * z23.x + xv.x * u0.z + xv.y * u1.z + xv.z * u2.z + xv.w * u3.z + bb.z, 0.f);
        v.w = fmaxf(s * z23.y + xv.x * u0.w + xv.y * u1.w + xv.z * u2.w + xv.w * u3.w + bb.w, 0.f);
        stcs4(out_h3 + (size_t)i * 512 + n, v);
        stcs4(out_cat + (size_t)i * 516 + n, v);
        float4 r0 = __ldg((const float4*)(w4 + (size_t)(n + 0) * 4));
        float4 r1 = __ldg((const float4*)(w4 + (size_t)(n + 1) * 4));
        float4 r2 = __ldg((const float4*)(w4 + (size_t)(n + 2) * 4));
        float4 r3 = __ldg((const float4*)(w4 + (size_t)(n + 3) * 4));
        h4acc.x += v.x * r0.x + v.y * r1.x + v.z * r2.x + v.w * r3.x;
        h4acc.y += v.x * r0.y + v.y * r1.y + v.z * r2.y + v.w * r3.y;
        h4acc.z += v.x * r0.z + v.y * r1.z + v.z * r2.z + v.w * r3.z;
        h4acc.w += v.x * r0.w + v.y * r1.w + v.z * r2.w + v.w * r3.w;
    }
#pragma unroll
    for (int off = 16; off > 0; off >>= 1) {
        h4acc.x += __shfl_xor_sync(0xFFFFFFFFu, h4acc.x, off);
        h4acc.y += __shfl_xor_sync(0xFFFFFFFFu, h4acc.y, off);
        h4acc.z += __shfl_xor_sync(0xFFFFFFFFu, h4acc.z, off);
        h4acc.w += __shfl_xor_sync(0xFFFFFFFFu, h4acc.w, off);
    }
    if (lane == 0) {
        float4 t0 = __ldg((const float4*)(w4 + (size_t)512 * 4));
        float4 t1 = __ldg((const float4*)(w4 + (size_t)513 * 4));
        float4 t2 = __ldg((const float4*)(w4 + (size_t)514 * 4));
        float4 t3 = __ldg((const float4*)(w4 + (size_t)515 * 4));
        float4 bb = __ldg((const float4*)b4);
        h4acc.x += xv.x * t0.x + xv.y * t1.x + xv.z * t2.x + xv.w * t3.x + bb.x;
        h4acc.y += xv.x * t0.y + xv.y * t1.y + xv.z * t2.y + xv.w * t3.y + bb.y;
        h4acc.z += xv.x * t0.z + xv.y * t1.z + xv.z * t2.z + xv.w * t3.z + bb.z;
        h4acc.w += xv.x * t0.w + xv.y * t1.w + xv.z * t2.w + xv.w * t3.w + bb.w;
        stcs4(logits + (size_t)i * 4, h4acc);
        stcs4(h4out + (size_t)i * 4, h4acc);
    } else if (lane == 1) {
        stcs4(out_cat + (size_t)i * 516 + 512, xv);
    }
}

// ---------------------------------------------------------------------------
extern "C" void kernel_launch(void* const* d_in, const int* in_sizes, int n_in,
                              void* d_out, int out_size) {
    const float* feature  = (const float*)d_in[0];
    const float* x3       = (const float*)d_in[1];
    const int*   adj_rows = (const int*)d_in[2];
    const int*   adj_cols = (const int*)d_in[3];
    const float* adj_vals = (const float*)d_in[4];
    // d_in[5] = bing_rows (arange, unused)
    const int*   bing_cols = (const int*)d_in[6];
    const float* bing_vals = (const float*)d_in[7];
    const float* w1 = (const float*)d_in[8];
    const float* b1 = (const float*)d_in[9];
    const float* w2 = (const float*)d_in[10];
    const float* b2 = (const float*)d_in[11];
    const float* w3 = (const float*)d_in[12];
    const float* b3 = (const float*)d_in[13];
    const float* w4 = (const float*)d_in[14];
    const float* b4 = (const float*)d_in[15];
    float* out = (float*)d_out;
    const int nE = in_sizes[2];
    const int EB = (nE + 255) / 256;

    float *AF;
    __half *Zh, *h1h, *AH1h, *H2h, *Wt2hi, *Wt2lo, *Wthi, *Wtlo;
    int *cnt, *rowptr, *fill, *bsum;
    int2 *edge;
    cudaGetSymbolAddress((void**)&AF, g_AF);
    cudaGetSymbolAddress((void**)&Zh, g_Zh);
    cudaGetSymbolAddress((void**)&cnt, g_cnt);
    cudaGetSymbolAddress((void**)&rowptr, g_rowptr);
    cudaGetSymbolAddress((void**)&fill, g_fill);
    cudaGetSymbolAddress((void**)&edge, g_edge);
    cudaGetSymbolAddress((void**)&bsum, g_bsum);
    cudaGetSymbolAddress((void**)&h1h, g_h1h);
    cudaGetSymbolAddress((void**)&AH1h, g_AH1h);
    cudaGetSymbolAddress((void**)&H2h, g_H2h);
    cudaGetSymbolAddress((void**)&Wt2hi, g_Wt2hi);
    cudaGetSymbolAddress((void**)&Wt2lo, g_Wt2lo);
    cudaGetSymbolAddress((void**)&Wthi, g_Wthi);
    cudaGetSymbolAddress((void**)&Wtlo, g_Wtlo);

    cudaFuncSetAttribute(gemm2_mma, cudaFuncAttributeMaxDynamicSharedMemorySize, ZS_TOTAL);
    cudaFuncSetAttribute(gemmZ_mma, cudaFuncAttributeMaxDynamicSharedMemorySize, ZS_TOTAL);

    cudaMemsetAsync(AF, 0, (size_t)N_POOL * 4 * sizeof(float));
    cudaMemsetAsync(cnt, 0, (size_t)N_POOL * sizeof(int));

    // CSR build (multi-block scan; scan_final also seeds fill)
    count_kernel<<<EB, 256>>>(adj_rows, cnt, nE);
    scan_reduce<<<SCAN_B, 1024>>>(cnt, bsum, N_POOL);
    scan_tops<<<1, 128>>>(bsum, rowptr + N_POOL, SCAN_B);
    scan_final<<<SCAN_B, 1024>>>(cnt, bsum, rowptr, fill, N_POOL);
    // edge scatter (packed) + fused spmm4 (AF)
    build_kernel<<<EB, 256>>>(adj_rows, adj_cols, adj_vals, fill, edge, feature, AF, nE);

    // weight converts (single launch)
    convert_w_kernel<<<(256 * 128 + 512 * 256 + 255) / 256, 256>>>(w2, w3, Wt2hi, Wt2lo,
                                                                   Wthi, Wtlo);

    // K2: h1cat -> d_out H1 region (.cs) + dense fp16 copy
    h1_kernel<<<N_POOL, 128>>>(AF, feature, w1, b1, out + OFF_H1, h1h);

    // K3: AH1 = csr-spmm(adj, h1h) -> fp16
    spmm128_csr<<<(N_POOL * 32 + 255) / 256, 256>>>(rowptr, edge, h1h, AH1h);

    // K4: h2 via fp16 tensor cores -> fp16
    gemm2_mma<<<dim3(2, M_PAD / 128), 256, ZS_TOTAL>>>(AH1h, Wt2hi, Wt2lo,
                                                       AF, w2, b2, H2h, N_POOL);

    // K5: Z = h2 @ w3a via fp16 tensor cores -> fp16
    gemmZ_mma<<<dim3(4, M_PAD / 128), 256, ZS_TOTAL>>>(H2h, Wthi, Wtlo, Zh, N_POOL);

    // K6: unpool (warp-per-point, fp16 Z gather)
    unpool_kernel<<<(N_POINTS * 32 + 255) / 256, 256>>>(Zh, x3, bing_cols, bing_vals,
                                                        w3, b3, w4, b4,
                                                        out + OFF_H2OUT, out + OFF_H3CAT,
                                                        out + OFF_LOGITS, out + OFF_H4);
}

// round 17
// speedup vs baseline: 1.2294x; 1.1618x over previous
#include <cuda_runtime.h>
#include <cuda_bf16.h>
#include <cuda_fp16.h>
#include <cstddef>
#include <cstdint>

// ---------------------------------------------------------------------------
// GcnNet restructured (round 17 = R16 + persistent-warp unpool):
//   CSR  = counting-sort of adj edges by row (multi-block scan); spmm4 fused
//   h1   = relu(AF @ w1 + b1); h1cat -> d_out (.cs); PLUS dense fp16 copy h1h
//   AH1  = csr-spmm(adj, h1h) -> fp16 single
//   h2   = relu(AH1 @ w2[:128] + AF @ w2[128:] + b2) via fp16 mma (B hi/lo)
//   Z    = h2 @ w3[0:256] via fp16 mma (B hi/lo) -> fp16 (L2-resident)
//   h3   = unpool: persistent warps, ALL weights hoisted to registers,
//          shuffle-only h4 reduce, streaming stores
// Output layout (floats): [logits | h1cat | h2_out(=h3) | h3_cat | h4]
// ---------------------------------------------------------------------------

#define N_POOL   100000
#define N_POINTS 400000
#define N_EDGES  3200000
#define M_PAD    100096   // 782 * 128
#define SCAN_B   98       // ceil(100000/1024)

static const size_t OFF_LOGITS = 0;
static const size_t OFF_H1     = (size_t)N_POINTS * 4;
static const size_t OFF_H2OUT  = OFF_H1 + (size_t)N_POOL * 132;
static const size_t OFF_H3CAT  = OFF_H2OUT + (size_t)N_POINTS * 512;
static const size_t OFF_H4     = OFF_H3CAT + (size_t)N_POINTS * 516;

// scratch (no cudaMalloc allowed). __device__ globals are zero-initialized.
__device__ float g_AF[(size_t)N_POOL * 4];
__device__ int   g_cnt[N_POOL];
__device__ int   g_rowptr[N_POOL + 1];
__device__ int   g_fill[N_POOL];
__device__ int   g_bsum[SCAN_B];
__device__ int2  g_edge[N_EDGES];   // (col, val-as-int)
__device__ __half g_h1h[(size_t)N_POOL * 128];   // dense fp16 gather copy
__device__ __half g_AH1h[(size_t)M_PAD * 128];   // fp16 single
__device__ __half g_H2h[(size_t)M_PAD * 256];    // fp16 single
__device__ __half g_Wt2hi[(size_t)256 * 128];    // w2[0:128]^T K-contig fp16 hi
__device__ __half g_Wt2lo[(size_t)256 * 128];    // fp16 lo
__device__ __half g_Wthi[(size_t)512 * 256];     // w3[0:256]^T K-contig fp16 hi
__device__ __half g_Wtlo[(size_t)512 * 256];     // fp16 lo
__device__ __half g_Zh[(size_t)N_POOL * 512];    // Z in fp16 (L2-resident)

// ------------------------------ helpers ------------------------------------
__device__ __forceinline__ uint32_t smem_to_u32(const void* p) {
    uint32_t a;
    asm("{ .reg .u64 t; cvta.to.shared.u64 t, %1; cvt.u32.u64 %0, t; }" : "=r"(a) : "l"(p));
    return a;
}
__device__ __forceinline__ void ldsm_x4(uint32_t& r0, uint32_t& r1, uint32_t& r2, uint32_t& r3,
                                        uint32_t addr) {
    asm volatile("ldmatrix.sync.aligned.m8n8.x4.shared.b16 {%0,%1,%2,%3}, [%4];"
                 : "=r"(r0), "=r"(r1), "=r"(r2), "=r"(r3) : "r"(addr));
}
__device__ __forceinline__ void mma_f16(float& c0, float& c1, float& c2, float& c3,
                                        uint32_t a0, uint32_t a1, uint32_t a2, uint32_t a3,
                                        uint32_t b0, uint32_t b1) {
    asm volatile("mma.sync.aligned.m16n8k16.row.col.f32.f16.f16.f32 "
                 "{%0,%1,%2,%3}, {%4,%5,%6,%7}, {%8,%9}, {%0,%1,%2,%3};"
                 : "+f"(c0), "+f"(c1), "+f"(c2), "+f"(c3)
                 : "r"(a0), "r"(a1), "r"(a2), "r"(a3), "r"(b0), "r"(b1));
}
__device__ __forceinline__ void red_add_v4(float* p, float a, float b, float c, float d) {
    asm volatile("red.global.add.v4.f32 [%0], {%1, %2, %3, %4};"
                 :: "l"(p), "f"(a), "f"(b), "f"(c), "f"(d) : "memory");
}
__device__ __forceinline__ void stcs4(float* p, float4 v) {
    asm volatile("st.global.cs.v4.f32 [%0], {%1, %2, %3, %4};"
                 :: "l"(p), "f"(v.x), "f"(v.y), "f"(v.z), "f"(v.w) : "memory");
}
__device__ __forceinline__ void stcs1(float* p, float v) {
    asm volatile("st.global.cs.f32 [%0], %1;" :: "l"(p), "f"(v) : "memory");
}

// --------------------------- CSR build -------------------------------------
__global__ void count_kernel(const int* __restrict__ keys, int* __restrict__ cnt, int n) {
    int e = blockIdx.x * blockDim.x + threadIdx.x;
    if (e < n) atomicAdd(cnt + __ldg(keys + e), 1);
}

__global__ void scan_reduce(const int* __restrict__ cnt, int* __restrict__ bsum, int n) {
    __shared__ int s[32];
    int tid = threadIdx.x, lane = tid & 31, wid = tid >> 5;
    int i = blockIdx.x * 1024 + tid;
    int v = (i < n) ? cnt[i] : 0;
#pragma unroll
    for (int off = 16; off > 0; off >>= 1) v += __shfl_down_sync(0xFFFFFFFFu, v, off);
    if (lane == 0) s[wid] = v;
    __syncthreads();
    if (wid == 0) {
        int x = s[lane];
#pragma unroll
        for (int off = 16; off > 0; off >>= 1) x += __shfl_down_sync(0xFFFFFFFFu, x, off);
        if (lane == 0) bsum[blockIdx.x] = x;
    }
}

__global__ void scan_tops(int* __restrict__ bsum, int* __restrict__ rowptr_last, int nb) {
    __shared__ int s[128];
    int t = threadIdx.x;  // 128 threads
    int v = (t < nb) ? bsum[t] : 0;
    s[t] = v;
    __syncthreads();
    for (int off = 1; off < 128; off <<= 1) {
        int x = (t >= off) ? s[t - off] : 0;
        __syncthreads();
        s[t] += x;
        __syncthreads();
    }
    if (t < nb) bsum[t] = s[t] - v;             // exclusive
    if (t == nb - 1) *rowptr_last = s[t];       // total -> rowptr[N_POOL]
}

__global__ void scan_final(const int* __restrict__ cnt, const int* __restrict__ bsum,
                           int* __restrict__ rowptr, int* __restrict__ fill, int n) {
    __shared__ int ws[32];
    int tid = threadIdx.x, lane = tid & 31, wid = tid >> 5;
    int i = blockIdx.x * 1024 + tid;
    int v = (i < n) ? cnt[i] : 0;
    int inc = v;
#pragma unroll
    for (int off = 1; off < 32; off <<= 1) {
        int x = __shfl_up_sync(0xFFFFFFFFu, inc, off);
        if (lane >= off) inc += x;
    }
    if (lane == 31) ws[wid] = inc;
    __syncthreads();
    if (wid == 0) {
        int x = ws[lane];
#pragma unroll
        for (int off = 1; off < 32; off <<= 1) {
            int y = __shfl_up_sync(0xFFFFFFFFu, x, off);
            if (lane >= off) x += y;
        }
        ws[lane] = x;
    }
    __syncthreads();
    int woff = (wid > 0) ? ws[wid - 1] : 0;
    if (i < n) {
        int p = inc - v + woff + __ldg(bsum + blockIdx.x);
        rowptr[i] = p;
        fill[i] = p;
    }
}

// edge scatter (packed int2) fused with spmm4 (AF = A @ feature)
__global__ void build_kernel(const int* __restrict__ rows, const int* __restrict__ cols,
                             const float* __restrict__ vals, int* __restrict__ fill,
                             int2* __restrict__ edge,
                             const float* __restrict__ F, float* __restrict__ AF, int nE) {
    int e = blockIdx.x * blockDim.x + threadIdx.x;
    if (e >= nE) return;
    int r = __ldg(rows + e);
    int c = __ldg(cols + e);
    float v = __ldg(vals + e);
    int pos = atomicAdd(fill + r, 1);
    edge[pos] = make_int2(c, __float_as_int(v));
    float4 f = *(const float4*)(F + (size_t)c * 4);
    red_add_v4(AF + (size_t)r * 4, v * f.x, v * f.y, v * f.z, v * f.w);
}

// ------------- K2: h1 = relu(AF@w1+b1) -> h1cat (.cs) + fp16 copy ----------
__global__ void h1_kernel(const float* __restrict__ AF, const float* __restrict__ F,
                          const float* __restrict__ w1, const float* __restrict__ b1,
                          float* __restrict__ out_h1, __half* __restrict__ h1h) {
    int r = blockIdx.x;
    int j = threadIdx.x;  // 128
    float4 a = *(const float4*)(AF + (size_t)r * 4);
    float s = __ldg(b1 + j)
            + a.x * __ldg(w1 + j)
            + a.y * __ldg(w1 + 128 + j)
            + a.z * __ldg(w1 + 256 + j)
            + a.w * __ldg(w1 + 384 + j);
    s = fmaxf(s, 0.f);
    float* row = out_h1 + (size_t)r * 132;
    stcs1(row + j, s);                       // final output; never re-read
    h1h[(size_t)r * 128 + j] = __float2half(s);
    if (j < 4) stcs1(row + 128 + j, F[(size_t)r * 4 + j]);
}

// ----------------- K3: AH1 = csr-spmm(adj, h1h) -> fp16 single -------------
__global__ __launch_bounds__(256)
void spmm128_csr(const int* __restrict__ rowptr, const int2* __restrict__ edge,
                 const __half* __restrict__ h1h, __half* __restrict__ AH1h) {
    int r = (blockIdx.x * blockDim.x + threadIdx.x) >> 5;
    if (r >= N_POOL) return;
    int lane = threadIdx.x & 31;
    int start = __ldg(rowptr + r), end = __ldg(rowptr + r + 1);
    float4 acc = make_float4(0.f, 0.f, 0.f, 0.f);
    const int loff = lane * 4;
    for (int base = start; base < end; base += 32) {
        int n = min(32, end - base);
        int2 ev = make_int2(0, 0);
        if (lane < n) ev = __ldg(edge + base + lane);
        int j = 0;
        for (; j + 8 <= n; j += 8) {
            int cc[8]; float vv[8]; uint2 uu[8];
#pragma unroll
            for (int q = 0; q < 8; q++) {
                cc[q] = __shfl_sync(0xFFFFFFFFu, ev.x, j + q);
                vv[q] = __int_as_float(__shfl_sync(0xFFFFFFFFu, ev.y, j + q));
            }
#pragma unroll
            for (int q = 0; q < 8; q++)
                uu[q] = *(const uint2*)(h1h + (size_t)cc[q] * 128 + loff);
#pragma unroll
            for (int q = 0; q < 8; q++) {
                float2 f01 = __half22float2(*reinterpret_cast<__half2*>(&uu[q].x));
                float2 f23 = __half22float2(*reinterpret_cast<__half2*>(&uu[q].y));
                acc.x += vv[q] * f01.x;
                acc.y += vv[q] * f01.y;
                acc.z += vv[q] * f23.x;
                acc.w += vv[q] * f23.y;
            }
        }
        for (; j < n; j++) {
            int cj = __shfl_sync(0xFFFFFFFFu, ev.x, j);
            float vj = __int_as_float(__shfl_sync(0xFFFFFFFFu, ev.y, j));
            uint2 u = *(const uint2*)(h1h + (size_t)cj * 128 + loff);
            float2 f01 = __half22float2(*reinterpret_cast<__half2*>(&u.x));
            float2 f23 = __half22float2(*reinterpret_cast<__half2*>(&u.y));
            acc.x += vj * f01.x; acc.y += vj * f01.y;
            acc.z += vj * f23.x; acc.w += vj * f23.y;
        }
    }
    union { __half2 h2[2]; uint2 u; } p;
    p.h2[0] = __floats2half2_rn(acc.x, acc.y);
    p.h2[1] = __floats2half2_rn(acc.z, acc.w);
    *(uint2*)(AH1h + (size_t)r * 128 + loff) = p.u;
}

// ------------- converts: w2^T and w3^T to fp16 hi/lo (one launch) ----------
__global__ void convert_w_kernel(const float* __restrict__ w2, const float* __restrict__ w3,
                                 __half* __restrict__ w2hi, __half* __restrict__ w2lo,
                                 __half* __restrict__ w3hi, __half* __restrict__ w3lo) {
    int t = blockIdx.x * blockDim.x + threadIdx.x;
    if (t < 256 * 128) {
        int n = t >> 7, k = t & 127;
        float v = __ldg(w2 + (size_t)k * 256 + n);
        __half h = __float2half_rn(v);
        w2hi[t] = h;
        w2lo[t] = __float2half_rn(v - __half2float(h));
    }
    int t3 = t - 256 * 128;
    if (t3 >= 0 && t3 < 512 * 256) {
        int n = t3 >> 8, k = t3 & 255;
        float v = __ldg(w3 + (size_t)k * 512 + n);
        __half h = __float2half_rn(v);
        w3hi[t3] = h;
        w3lo[t3] = __float2half_rn(v - __half2float(h));
    }
}

// ===========================================================================
// fp16 mma.sync GEMM bodies: block 128x128, 8 warps (2x4), warp 64x32, BK=32
// ===========================================================================
#define ZS_STRIDE 40
#define ZS_TBYTES (128 * ZS_STRIDE * 2)
#define ZS_STAGE  (3 * ZS_TBYTES)
#define ZS_TOTAL  (2 * ZS_STAGE)   // 61440

// --------------------------- K4: gemm2 via fp16 mma ------------------------
__global__ __launch_bounds__(256)
void gemm2_mma(const __half* __restrict__ A, const __half* __restrict__ Bhi,
               const __half* __restrict__ Blo,
               const float* __restrict__ AF, const float* __restrict__ w2,
               const float* __restrict__ b2, __half* __restrict__ H2h, int M) {
    extern __shared__ char sm[];
    const int tid = threadIdx.x;
    const int lane = tid & 31, wid = tid >> 5;
    const int warp_m = (wid & 1) * 64;
    const int warp_n = (wid >> 1) * 32;
    const int row0 = blockIdx.y * 128;
    const int col0 = blockIdx.x * 128;
    const uint32_t sb = smem_to_u32(sm);

    const int st_row = tid >> 2;
    const int st_c8  = (tid & 3) << 3;

    auto stage = [&](int kt, int buf) {
        const int k0 = kt * 32;
        char* base = sm + buf * ZS_STAGE;
#pragma unroll
        for (int it = 0; it < 2; it++) {
            int row = st_row + it * 64;
            size_t ga = (size_t)(row0 + row) * 128 + k0 + st_c8;
            size_t gb = (size_t)(col0 + row) * 128 + k0 + st_c8;
            uint32_t so = (uint32_t)(row * ZS_STRIDE + st_c8) * 2;
            *(uint4*)(base + 0 * ZS_TBYTES + so) = *(const uint4*)(A + ga);
            *(uint4*)(base + 1 * ZS_TBYTES + so) = *(const uint4*)(Bhi + gb);
            *(uint4*)(base + 2 * ZS_TBYTES + so) = *(const uint4*)(Blo + gb);
        }
    };

    float acc[4][4][4];
#pragma unroll
    for (int i = 0; i < 4; i++)
#pragma unroll
        for (int j = 0; j < 4; j++)
#pragma unroll
            for (int q = 0; q < 4; q++) acc[i][j][q] = 0.f;

    const int a_row_l = (lane & 7) + ((lane >> 3) & 1) * 8;
    const int a_col_l = (lane >> 4) * 8;
    const int b_row_l = lane & 7;
    const int b_n_l   = (lane >> 4) * 8;
    const int b_k_l   = ((lane >> 3) & 1) * 8;

    stage(0, 0);
    __syncthreads();

    for (int kt = 0; kt < 4; kt++) {
        if (kt < 3) stage(kt + 1, (kt + 1) & 1);
        const uint32_t abase = sb + (kt & 1) * ZS_STAGE;
        const uint32_t bbase = abase + 1 * ZS_TBYTES;
#pragma unroll
        for (int ks = 0; ks < 2; ks++) {
            const int kl = ks * 16;
            uint32_t av[4][4];
#pragma unroll
            for (int mf = 0; mf < 4; mf++) {
                uint32_t ao = abase +
                    (uint32_t)((warp_m + mf * 16 + a_row_l) * ZS_STRIDE + kl + a_col_l) * 2;
                ldsm_x4(av[mf][0], av[mf][1], av[mf][2], av[mf][3], ao);
            }
            uint32_t bh[2][4], bl[2][4];
#pragma unroll
            for (int ng = 0; ng < 2; ng++) {
                uint32_t bo = bbase +
                    (uint32_t)((warp_n + ng * 16 + b_n_l + b_row_l) * ZS_STRIDE + kl + b_k_l) * 2;
                ldsm_x4(bh[ng][0], bh[ng][1], bh[ng][2], bh[ng][3], bo);
                ldsm_x4(bl[ng][0], bl[ng][1], bl[ng][2], bl[ng][3], bo + ZS_TBYTES);
            }
#pragma unroll
            for (int mf = 0; mf < 4; mf++) {
#pragma unroll
                for (int n = 0; n < 4; n++) {
                    const int ng = n >> 1, hf = (n & 1) * 2;
                    float* c = acc[mf][n];
                    mma_f16(c[0], c[1], c[2], c[3],
                            av[mf][0], av[mf][1], av[mf][2], av[mf][3],
                            bh[ng][hf], bh[ng][hf + 1]);
                    mma_f16(c[0], c[1], c[2], c[3],
                            av[mf][0], av[mf][1], av[mf][2], av[mf][3],
                            bl[ng][hf], bl[ng][hf + 1]);
                }
            }
        }
        __syncthreads();
    }

    // epilogue: + AF @ w2[128:132] + b2, relu, fp16 store
    const int er = lane >> 2, ec = (lane & 3) * 2;
    float4 af[4][2];
#pragma unroll
    for (int mf = 0; mf < 4; mf++) {
        int r0g = row0 + warp_m + mf * 16 + er;
        af[mf][0] = (r0g < M)     ? *(const float4*)(AF + (size_t)r0g * 4)       : make_float4(0, 0, 0, 0);
        af[mf][1] = (r0g + 8 < M) ? *(const float4*)(AF + (size_t)(r0g + 8) * 4) : make_float4(0, 0, 0, 0);
    }
#pragma unroll
    for (int n = 0; n < 4; n++) {
        int cg = col0 + warp_n + n * 8 + ec;
        float wt[4][2];
#pragma unroll
        for (int k = 0; k < 4; k++) {
            wt[k][0] = __ldg(w2 + (size_t)(128 + k) * 256 + cg);
            wt[k][1] = __ldg(w2 + (size_t)(128 + k) * 256 + cg + 1);
        }
        float bb0 = __ldg(b2 + cg), bb1 = __ldg(b2 + cg + 1);
#pragma unroll
        for (int mf = 0; mf < 4; mf++) {
#pragma unroll
            for (int half = 0; half < 2; half++) {
                int g = row0 + warp_m + mf * 16 + er + half * 8;
                if (g >= M) continue;
                float4 a4 = af[mf][half];
                float t0 = a4.x * wt[0][0] + a4.y * wt[1][0] + a4.z * wt[2][0] + a4.w * wt[3][0];
                float t1 = a4.x * wt[0][1] + a4.y * wt[1][1] + a4.z * wt[2][1] + a4.w * wt[3][1];
                float v0 = fmaxf(acc[mf][n][half * 2 + 0] + bb0 + t0, 0.f);
                float v1 = fmaxf(acc[mf][n][half * 2 + 1] + bb1 + t1, 0.f);
                *(__half2*)(H2h + (size_t)g * 256 + cg) = __floats2half2_rn(v0, v1);
            }
        }
    }
}

// --------------------------- K5: Z = h2 @ w3a (fp16 mma) -> fp16 -----------
__global__ __launch_bounds__(256)
void gemmZ_mma(const __half* __restrict__ A, const __half* __restrict__ Bhi,
               const __half* __restrict__ Blo, __half* __restrict__ Zh, int M) {
    extern __shared__ char sm[];
    const int tid = threadIdx.x;
    const int lane = tid & 31, wid = tid >> 5;
    const int warp_m = (wid & 1) * 64;
    const int warp_n = (wid >> 1) * 32;
    const int row0 = blockIdx.y * 128;
    const int col0 = blockIdx.x * 128;
    const uint32_t sb = smem_to_u32(sm);

    const int st_row = tid >> 2;
    const int st_c8  = (tid & 3) << 3;

    auto stage = [&](int kt, int buf) {
        const int k0 = kt * 32;
        char* base = sm + buf * ZS_STAGE;
#pragma unroll
        for (int it = 0; it < 2; it++) {
            int row = st_row + it * 64;
            size_t ga = (size_t)(row0 + row) * 256 + k0 + st_c8;
            size_t gb = (size_t)(col0 + row) * 256 + k0 + st_c8;
            uint32_t so = (uint32_t)(row * ZS_STRIDE + st_c8) * 2;
            *(uint4*)(base + 0 * ZS_TBYTES + so) = *(const uint4*)(A + ga);
            *(uint4*)(base + 1 * ZS_TBYTES + so) = *(const uint4*)(Bhi + gb);
            *(uint4*)(base + 2 * ZS_TBYTES + so) = *(const uint4*)(Blo + gb);
        }
    };

    float acc[4][4][4];
#pragma unroll
    for (int i = 0; i < 4; i++)
#pragma unroll
        for (int j = 0; j < 4; j++)
#pragma unroll
            for (int q = 0; q < 4; q++) acc[i][j][q] = 0.f;

    const int a_row_l = (lane & 7) + ((lane >> 3) & 1) * 8;
    const int a_col_l = (lane >> 4) * 8;
    const int b_row_l = lane & 7;
    const int b_n_l   = (lane >> 4) * 8;
    const int b_k_l   = ((lane >> 3) & 1) * 8;

    stage(0, 0);
    __syncthreads();

    for (int kt = 0; kt < 8; kt++) {
        if (kt < 7) stage(kt + 1, (kt + 1) & 1);
        const uint32_t abase = sb + (kt & 1) * ZS_STAGE;
        const uint32_t bbase = abase + 1 * ZS_TBYTES;
#pragma unroll
        for (int ks = 0; ks < 2; ks++) {
            const int kl = ks * 16;
            uint32_t av[4][4];
#pragma unroll
            for (int mf = 0; mf < 4; mf++) {
                uint32_t ao = abase +
                    (uint32_t)((warp_m + mf * 16 + a_row_l) * ZS_STRIDE + kl + a_col_l) * 2;
                ldsm_x4(av[mf][0], av[mf][1], av[mf][2], av[mf][3], ao);
            }
            uint32_t bh[2][4], bl[2][4];
#pragma unroll
            for (int ng = 0; ng < 2; ng++) {
                uint32_t bo = bbase +
                    (uint32_t)((warp_n + ng * 16 + b_n_l + b_row_l) * ZS_STRIDE + kl + b_k_l) * 2;
                ldsm_x4(bh[ng][0], bh[ng][1], bh[ng][2], bh[ng][3], bo);
                ldsm_x4(bl[ng][0], bl[ng][1], bl[ng][2], bl[ng][3], bo + ZS_TBYTES);
            }
#pragma unroll
            for (int mf = 0; mf < 4; mf++) {
#pragma unroll
                for (int n = 0; n < 4; n++) {
                    const int ng = n >> 1, hf = (n & 1) * 2;
                    float* c = acc[mf][n];
                    mma_f16(c[0], c[1], c[2], c[3],
                            av[mf][0], av[mf][1], av[mf][2], av[mf][3],
                            bh[ng][hf], bh[ng][hf + 1]);
                    mma_f16(c[0], c[1], c[2], c[3],
                            av[mf][0], av[mf][1], av[mf][2], av[mf][3],
                            bl[ng][hf], bl[ng][hf + 1]);
                }
            }
        }
        __syncthreads();
    }

    const int er = lane >> 2, ec = (lane & 3) * 2;
#pragma unroll
    for (int mf = 0; mf < 4; mf++) {
        int r0g = row0 + warp_m + mf * 16 + er;
        int r1g = r0g + 8;
#pragma unroll
        for (int n = 0; n < 4; n++) {
            int cg = col0 + warp_n + n * 8 + ec;
            if (r0g < M)
                *(__half2*)(Zh + (size_t)r0g * 512 + cg) = __floats2half2_rn(acc[mf][n][0], acc[mf][n][1]);
            if (r1g < M)
                *(__half2*)(Zh + (size_t)r1g * 512 + cg) = __floats2half2_rn(acc[mf][n][2], acc[mf][n][3]);
        }
    }
}

// ----------- K6: unpool — persistent warps, weights in registers -----------
// Each warp grid-strides over points; lane owns columns {q*128+lane*4} forever.
// No block-level sync: h4 reduce is shuffle-only.
__global__ __launch_bounds__(256)
void unpool_kernel(const __half* __restrict__ Zh, const float* __restrict__ x3,
                   const int* __restrict__ bcols, const float* __restrict__ bvals,
                   const float* __restrict__ w3, const float* __restrict__ b3,
                   const float* __restrict__ w4, const float* __restrict__ b4,
                   float* __restrict__ out_h3, float* __restrict__ out_cat,
                   float* __restrict__ logits, float* __restrict__ h4out) {
    const int lane = threadIdx.x & 31;
    const int gwarp = (blockIdx.x * blockDim.x + threadIdx.x) >> 5;
    const int nwarps = (gridDim.x * blockDim.x) >> 5;
    const float* w3t = w3 + (size_t)256 * 512;

    // hoisted per-lane weights: 36 float4
    float4 u0[4], u1[4], u2[4], u3[4], bb[4], r0[4], r1[4], r2[4], r3[4];
#pragma unroll
    for (int q = 0; q < 4; q++) {
        int n = q * 128 + lane * 4;
        u0[q] = __ldg((const float4*)(w3t + 0 * 512 + n));
        u1[q] = __ldg((const float4*)(w3t + 1 * 512 + n));
        u2[q] = __ldg((const float4*)(w3t + 2 * 512 + n));
        u3[q] = __ldg((const float4*)(w3t + 3 * 512 + n));
        bb[q] = __ldg((const float4*)(b3 + n));
        r0[q] = __ldg((const float4*)(w4 + (size_t)(n + 0) * 4));
        r1[q] = __ldg((const float4*)(w4 + (size_t)(n + 1) * 4));
        r2[q] = __ldg((const float4*)(w4 + (size_t)(n + 2) * 4));
        r3[q] = __ldg((const float4*)(w4 + (size_t)(n + 3) * 4));
    }
    const float4 t0 = __ldg((const float4*)(w4 + (size_t)512 * 4));
    const float4 t1 = __ldg((const float4*)(w4 + (size_t)513 * 4));
    const float4 t2 = __ldg((const float4*)(w4 + (size_t)514 * 4));
    const float4 t3 = __ldg((const float4*)(w4 + (size_t)515 * 4));
    const float4 b4v = __ldg((const float4*)b4);

    for (int i = gwarp; i < N_POINTS; i += nwarps) {
        int c = __ldg(bcols + i);
        float s = __ldg(bvals + i);
        float4 xv = __ldg((const float4*)(x3 + (size_t)i * 4));

        float4 h4acc = make_float4(0.f, 0.f, 0.f, 0.f);
#pragma unroll
        for (int q = 0; q < 4; q++) {
            int n = q * 128 + lane * 4;
            uint2 zu = __ldg((const uint2*)(Zh + (size_t)c * 512 + n));
            float2 z01 = __half22float2(*reinterpret_cast<__half2*>(&zu.x));
            float2 z23 = __half22float2(*reinterpret_cast<__half2*>(&zu.y));
            float4 v;
            v.x = fmaxf(s * z01.x + xv.x * u0[q].x + xv.y * u1[q].x + xv.z * u2[q].x + xv.w * u3[q].x + bb[q].x, 0.f);
            v.y = fmaxf(s * z01.y + xv.x * u0[q].y + xv.y * u1[q].y + xv.z * u2[q].y + xv.w * u3[q].y + bb[q].y, 0.f);
            v.z = fmaxf(s * z23.x + xv.x * u0[q].z + xv.y * u1[q].z + xv.z * u2[q].z + xv.w * u3[q].z + bb[q].z, 0.f);
            v.w = fmaxf(s * z23.y + xv.x * u0[q].w + xv.y * u1[q].w + xv.z * u2[q].w + xv.w * u3[q].w + bb[q].w, 0.f);
            stcs4(out_h3 + (size_t)i * 512 + n, v);
            stcs4(out_cat + (size_t)i * 516 + n, v);
            h4acc.x += v.x * r0[q].x + v.y * r1[q].x + v.z * r2[q].x + v.w * r3[q].x;
            h4acc.y += v.x * r0[q].y + v.y * r1[q].y + v.z * r2[q].y + v.w * r3[q].y;
            h4acc.z += v.x * r0[q].z + v.y * r1[q].z + v.z * r2[q].z + v.w * r3[q].z;
            h4acc.w += v.x * r0[q].w + v.y * r1[q].w + v.z * r2[q].w + v.w * r3[q].w;
        }
#pragma unroll
        for (int off = 16; off > 0; off >>= 1) {
            h4acc.x += __shfl_xor_sync(0xFFFFFFFFu, h4acc.x, off);
            h4acc.y += __shfl_xor_sync(0xFFFFFFFFu, h4acc.y, off);
            h4acc.z += __shfl_xor_sync(0xFFFFFFFFu, h4acc.z, off);
            h4acc.w += __shfl_xor_sync(0xFFFFFFFFu, h4acc.w, off);
        }
        if (lane == 0) {
            h4acc.x += xv.x * t0.x + xv.y * t1.x + xv.z * t2.x + xv.w * t3.x + b4v.x;
            h4acc.y += xv.x * t0.y + xv.y * t1.y + xv.z * t2.y + xv.w * t3.y + b4v.y;
            h4acc.z += xv.x * t0.z + xv.y * t1.z + xv.z * t2.z + xv.w * t3.z + b4v.z;
            h4acc.w += xv.x * t0.w + xv.y * t1.w + xv.z * t2.w + xv.w * t3.w + b4v.w;
            stcs4(logits + (size_t)i * 4, h4acc);
            stcs4(h4out + (size_t)i * 4, h4acc);
        } else if (lane == 1) {
            stcs4(out_cat + (size_t)i * 516 + 512, xv);
        }
    }
}

// ---------------------------------------------------------------------------
extern "C" void kernel_launch(void* const* d_in, const int* in_sizes, int n_in,
                              void* d_out, int out_size) {
    const float* feature  = (const float*)d_in[0];
    const float* x3       = (const float*)d_in[1];
    const int*   adj_rows = (const int*)d_in[2];
    const int*   adj_cols = (const int*)d_in[3];
    const float* adj_vals = (const float*)d_in[4];
    // d_in[5] = bing_rows (arange, unused)
    const int*   bing_cols = (const int*)d_in[6];
    const float* bing_vals = (const float*)d_in[7];
    const float* w1 = (const float*)d_in[8];
    const float* b1 = (const float*)d_in[9];
    const float* w2 = (const float*)d_in[10];
    const float* b2 = (const float*)d_in[11];
    const float* w3 = (const float*)d_in[12];
    const float* b3 = (const float*)d_in[13];
    const float* w4 = (const float*)d_in[14];
    const float* b4 = (const float*)d_in[15];
    float* out = (float*)d_out;
    const int nE = in_sizes[2];
    const int EB = (nE + 255) / 256;

    float *AF;
    __half *Zh, *h1h, *AH1h, *H2h, *Wt2hi, *Wt2lo, *Wthi, *Wtlo;
    int *cnt, *rowptr, *fill, *bsum;
    int2 *edge;
    cudaGetSymbolAddress((void**)&AF, g_AF);
    cudaGetSymbolAddress((void**)&Zh, g_Zh);
    cudaGetSymbolAddress((void**)&cnt, g_cnt);
    cudaGetSymbolAddress((void**)&rowptr, g_rowptr);
    cudaGetSymbolAddress((void**)&fill, g_fill);
    cudaGetSymbolAddress((void**)&edge, g_edge);
    cudaGetSymbolAddress((void**)&bsum, g_bsum);
    cudaGetSymbolAddress((void**)&h1h, g_h1h);
    cudaGetSymbolAddress((void**)&AH1h, g_AH1h);
    cudaGetSymbolAddress((void**)&H2h, g_H2h);
    cudaGetSymbolAddress((void**)&Wt2hi, g_Wt2hi);
    cudaGetSymbolAddress((void**)&Wt2lo, g_Wt2lo);
    cudaGetSymbolAddress((void**)&Wthi, g_Wthi);
    cudaGetSymbolAddress((void**)&Wtlo, g_Wtlo);

    cudaFuncSetAttribute(gemm2_mma, cudaFuncAttributeMaxDynamicSharedMemorySize, ZS_TOTAL);
    cudaFuncSetAttribute(gemmZ_mma, cudaFuncAttributeMaxDynamicSharedMemorySize, ZS_TOTAL);

    cudaMemsetAsync(AF, 0, (size_t)N_POOL * 4 * sizeof(float));
    cudaMemsetAsync(cnt, 0, (size_t)N_POOL * sizeof(int));

    // CSR build (multi-block scan; scan_final also seeds fill)
    count_kernel<<<EB, 256>>>(adj_rows, cnt, nE);
    scan_reduce<<<SCAN_B, 1024>>>(cnt, bsum, N_POOL);
    scan_tops<<<1, 128>>>(bsum, rowptr + N_POOL, SCAN_B);
    scan_final<<<SCAN_B, 1024>>>(cnt, bsum, rowptr, fill, N_POOL);
    // edge scatter (packed) + fused spmm4 (AF)
    build_kernel<<<EB, 256>>>(adj_rows, adj_cols, adj_vals, fill, edge, feature, AF, nE);

    // weight converts (single launch)
    convert_w_kernel<<<(256 * 128 + 512 * 256 + 255) / 256, 256>>>(w2, w3, Wt2hi, Wt2lo,
                                                                   Wthi, Wtlo);

    // K2: h1cat -> d_out H1 region (.cs) + dense fp16 copy
    h1_kernel<<<N_POOL, 128>>>(AF, feature, w1, b1, out + OFF_H1, h1h);

    // K3: AH1 = csr-spmm(adj, h1h) -> fp16
    spmm128_csr<<<(N_POOL * 32 + 255) / 256, 256>>>(rowptr, edge, h1h, AH1h);

    // K4: h2 via fp16 tensor cores -> fp16
    gemm2_mma<<<dim3(2, M_PAD / 128), 256, ZS_TOTAL>>>(AH1h, Wt2hi, Wt2lo,
                                                       AF, w2, b2, H2h, N_POOL);

    // K5: Z = h2 @ w3a via fp16 tensor cores -> fp16
    gemmZ_mma<<<dim3(4, M_PAD / 128), 256, ZS_TOTAL>>>(H2h, Wthi, Wtlo, Zh, N_POOL);

    // K6: unpool (persistent warps, hoisted weights)
    unpool_kernel<<<592, 256>>>(Zh, x3, bing_cols, bing_vals, w3, b3, w4, b4,
                                out + OFF_H2OUT, out + OFF_H3CAT,
                                out + OFF_LOGITS, out + OFF_H4);
}